// round 1
// baseline (speedup 1.0000x reference)
#include <cuda_runtime.h>
#include <math.h>

#define D_MODEL   1024
#define NUM_HEADS 16
#define D_HEAD    64
#define BATCH     4
#define SEQ       2048
#define M_TOT     (BATCH * SEQ)   // 8192

// Scratch (allocation-free: device globals). 4 x 32 MB.
__device__ float g_Q[M_TOT * D_MODEL];
__device__ float g_K[M_TOT * D_MODEL];
__device__ float g_V[M_TOT * D_MODEL];
__device__ float g_O[M_TOT * D_MODEL];

// ---------------------------------------------------------------------------
// C = A @ W^T + bias.  A:[M,1024] row-major, W:[1024,1024] row-major (torch
// Linear weight, so W^T indexing = W[n*K + k] -> NT gemm, both K-contiguous).
// 128x128 block, BK=8, 256 threads, 8x8 register tile per thread.
// blockIdx.z selects one of up to three (W, bias, C) triples (fused QKV).
// ---------------------------------------------------------------------------
__global__ __launch_bounds__(256) void sgemm_nt_bias(
    const float* __restrict__ A,
    const float* __restrict__ W0, const float* __restrict__ W1, const float* __restrict__ W2,
    const float* __restrict__ b0, const float* __restrict__ b1, const float* __restrict__ b2,
    float* __restrict__ C0, float* __restrict__ C1, float* __restrict__ C2)
{
    const float* W;
    const float* bias;
    float* C;
    if (blockIdx.z == 0)      { W = W0; bias = b0; C = C0; }
    else if (blockIdx.z == 1) { W = W1; bias = b1; C = C1; }
    else                      { W = W2; bias = b2; C = C2; }

    __shared__ float As[8 * 132];   // [k][m], padded stride 132 (16B-aligned rows)
    __shared__ float Bs[8 * 132];   // [k][n]

    const int tid = threadIdx.x;
    const int tx  = tid & 15;       // 0..15 -> n
    const int ty  = tid >> 4;       // 0..15 -> m
    const int m0  = blockIdx.y * 128;
    const int n0  = blockIdx.x * 128;

    // loader mapping: 256 threads x 1 float4 = 128 rows x 8 k
    const int lrow = tid >> 1;           // 0..127
    const int lvec = (tid & 1) * 4;      // 0 or 4
    const float* Ap = A + (size_t)(m0 + lrow) * D_MODEL + lvec;
    const float* Wp = W + (size_t)(n0 + lrow) * D_MODEL + lvec;

    float acc[8][8];
    #pragma unroll
    for (int i = 0; i < 8; i++)
        #pragma unroll
        for (int j = 0; j < 8; j++) acc[i][j] = 0.f;

    for (int k0 = 0; k0 < D_MODEL; k0 += 8) {
        float4 av = *(const float4*)(Ap + k0);
        float4 wv = *(const float4*)(Wp + k0);
        As[(lvec + 0) * 132 + lrow] = av.x;
        As[(lvec + 1) * 132 + lrow] = av.y;
        As[(lvec + 2) * 132 + lrow] = av.z;
        As[(lvec + 3) * 132 + lrow] = av.w;
        Bs[(lvec + 0) * 132 + lrow] = wv.x;
        Bs[(lvec + 1) * 132 + lrow] = wv.y;
        Bs[(lvec + 2) * 132 + lrow] = wv.z;
        Bs[(lvec + 3) * 132 + lrow] = wv.w;
        __syncthreads();

        #pragma unroll
        for (int k = 0; k < 8; k++) {
            float4 a0 = *(const float4*)&As[k * 132 + ty * 8];
            float4 a1 = *(const float4*)&As[k * 132 + ty * 8 + 4];
            float4 w0v = *(const float4*)&Bs[k * 132 + tx * 8];
            float4 w1v = *(const float4*)&Bs[k * 132 + tx * 8 + 4];
            float a[8]  = {a0.x, a0.y, a0.z, a0.w, a1.x, a1.y, a1.z, a1.w};
            float bb[8] = {w0v.x, w0v.y, w0v.z, w0v.w, w1v.x, w1v.y, w1v.z, w1v.w};
            #pragma unroll
            for (int i = 0; i < 8; i++)
                #pragma unroll
                for (int j = 0; j < 8; j++)
                    acc[i][j] = fmaf(a[i], bb[j], acc[i][j]);
        }
        __syncthreads();
    }

    float4 bv0 = *(const float4*)(bias + n0 + tx * 8);
    float4 bv1 = *(const float4*)(bias + n0 + tx * 8 + 4);
    #pragma unroll
    for (int i = 0; i < 8; i++) {
        int m = m0 + ty * 8 + i;
        float* cp = C + (size_t)m * D_MODEL + n0 + tx * 8;
        float4 r0 = make_float4(acc[i][0] + bv0.x, acc[i][1] + bv0.y,
                                acc[i][2] + bv0.z, acc[i][3] + bv0.w);
        float4 r1 = make_float4(acc[i][4] + bv1.x, acc[i][5] + bv1.y,
                                acc[i][6] + bv1.z, acc[i][7] + bv1.w);
        *(float4*)cp       = r0;
        *(float4*)(cp + 4) = r1;
    }
}

// ---------------------------------------------------------------------------
// Flash attention, fp32. One CTA = one (b, h) x 64 query rows. KV streamed in
// 64-row tiles through SMEM. 256 threads as 16x16; each thread owns a 4x4 tile
// of the 64x64 score/output blocks. Row groups live in half-warps -> shfl_xor
// reductions for online softmax (max & sum). Q/K/V read from [m][1024] layout.
// ---------------------------------------------------------------------------
__global__ __launch_bounds__(256) void flash_attn(
    const float* __restrict__ Q, const float* __restrict__ K,
    const float* __restrict__ V, float* __restrict__ O)
{
    extern __shared__ float sm[];
    float* Qs = sm;            // [d][r] transposed, 64x64
    float* Ks = sm + 4096;     // [d][c] transposed
    float* Vs = sm + 8192;     // [c][d] natural
    float* Ps = sm + 12288;    // [c][r] transposed

    const int tid = threadIdx.x;
    const int tx  = tid & 15;
    const int ty  = tid >> 4;
    const int b   = blockIdx.y >> 4;
    const int h   = blockIdx.y & 15;
    const int q0  = blockIdx.x * 64;

    const int lr  = tid >> 2;         // 0..63 (row within tile)
    const int ld0 = (tid & 3) * 16;   // 0,16,32,48 (d-group)

    // Q tile, transposed, pre-scaled by 1/sqrt(64)
    {
        const float* qp = Q + (size_t)(b * SEQ + q0 + lr) * D_MODEL + h * 64 + ld0;
        #pragma unroll
        for (int i = 0; i < 4; i++) {
            float4 v = *(const float4*)(qp + i * 4);
            int d = ld0 + i * 4;
            Qs[(d + 0) * 64 + lr] = v.x * 0.125f;
            Qs[(d + 1) * 64 + lr] = v.y * 0.125f;
            Qs[(d + 2) * 64 + lr] = v.z * 0.125f;
            Qs[(d + 3) * 64 + lr] = v.w * 0.125f;
        }
    }

    float o[4][4];
    float mrun[4], lrun[4];
    #pragma unroll
    for (int i = 0; i < 4; i++) {
        mrun[i] = -1e30f;
        lrun[i] = 0.f;
        #pragma unroll
        for (int j = 0; j < 4; j++) o[i][j] = 0.f;
    }

    for (int kt = 0; kt < SEQ / 64; kt++) {
        const int c0 = kt * 64;
        {
            const float* kp = K + (size_t)(b * SEQ + c0 + lr) * D_MODEL + h * 64 + ld0;
            const float* vp = V + (size_t)(b * SEQ + c0 + lr) * D_MODEL + h * 64 + ld0;
            #pragma unroll
            for (int i = 0; i < 4; i++) {
                int d = ld0 + i * 4;
                float4 kv = *(const float4*)(kp + i * 4);
                Ks[(d + 0) * 64 + lr] = kv.x;
                Ks[(d + 1) * 64 + lr] = kv.y;
                Ks[(d + 2) * 64 + lr] = kv.z;
                Ks[(d + 3) * 64 + lr] = kv.w;
                float4 vv = *(const float4*)(vp + i * 4);
                *(float4*)&Vs[lr * 64 + d] = vv;
            }
        }
        __syncthreads();

        // S = (Q * scale) @ K^T  -> 4x4 per thread
        float s[4][4];
        #pragma unroll
        for (int i = 0; i < 4; i++)
            #pragma unroll
            for (int j = 0; j < 4; j++) s[i][j] = 0.f;
        #pragma unroll 8
        for (int d = 0; d < 64; d++) {
            float4 a  = *(const float4*)&Qs[d * 64 + ty * 4];
            float4 bb = *(const float4*)&Ks[d * 64 + tx * 4];
            float av[4] = {a.x, a.y, a.z, a.w};
            float bv[4] = {bb.x, bb.y, bb.z, bb.w};
            #pragma unroll
            for (int i = 0; i < 4; i++)
                #pragma unroll
                for (int j = 0; j < 4; j++)
                    s[i][j] = fmaf(av[i], bv[j], s[i][j]);
        }

        // online softmax; row r = ty*4+i is spread over the 16 tx threads of a
        // half-warp (lane bits 0..3), so xor-shfl 1/2/4/8 reduces it.
        #pragma unroll
        for (int i = 0; i < 4; i++) {
            float mloc = fmaxf(fmaxf(s[i][0], s[i][1]), fmaxf(s[i][2], s[i][3]));
            #pragma unroll
            for (int off = 1; off < 16; off <<= 1)
                mloc = fmaxf(mloc, __shfl_xor_sync(0xffffffffu, mloc, off));
            float mnew = fmaxf(mrun[i], mloc);
            float corr = __expf(mrun[i] - mnew);
            float lloc = 0.f;
            #pragma unroll
            for (int j = 0; j < 4; j++) {
                s[i][j] = __expf(s[i][j] - mnew);
                lloc += s[i][j];
            }
            #pragma unroll
            for (int off = 1; off < 16; off <<= 1)
                lloc += __shfl_xor_sync(0xffffffffu, lloc, off);
            lrun[i] = lrun[i] * corr + lloc;
            mrun[i] = mnew;
            #pragma unroll
            for (int j = 0; j < 4; j++) {
                o[i][j] *= corr;
                Ps[(tx * 4 + j) * 64 + ty * 4 + i] = s[i][j];
            }
        }
        __syncthreads();

        // O += P @ V
        #pragma unroll 8
        for (int c = 0; c < 64; c++) {
            float4 a  = *(const float4*)&Ps[c * 64 + ty * 4];
            float4 bb = *(const float4*)&Vs[c * 64 + tx * 4];
            float av[4] = {a.x, a.y, a.z, a.w};
            float bv[4] = {bb.x, bb.y, bb.z, bb.w};
            #pragma unroll
            for (int i = 0; i < 4; i++)
                #pragma unroll
                for (int j = 0; j < 4; j++)
                    o[i][j] = fmaf(av[i], bv[j], o[i][j]);
        }
        __syncthreads();
    }

    // normalize and write attention output in model layout [m][1024]
    #pragma unroll
    for (int i = 0; i < 4; i++) {
        float inv = 1.f / lrun[i];
        int srow = q0 + ty * 4 + i;
        float4 r = make_float4(o[i][0] * inv, o[i][1] * inv,
                               o[i][2] * inv, o[i][3] * inv);
        *(float4*)&O[(size_t)(b * SEQ + srow) * D_MODEL + h * 64 + tx * 4] = r;
    }
}

// ---------------------------------------------------------------------------
extern "C" void kernel_launch(void* const* d_in, const int* in_sizes, int n_in,
                              void* d_out, int out_size)
{
    const float* x  = (const float*)d_in[0];
    const float* Wq = (const float*)d_in[1];
    const float* bq = (const float*)d_in[2];
    const float* Wk = (const float*)d_in[3];
    const float* bk = (const float*)d_in[4];
    const float* Wv = (const float*)d_in[5];
    const float* bv = (const float*)d_in[6];
    const float* Wo = (const float*)d_in[7];
    const float* bo = (const float*)d_in[8];

    float *Qd, *Kd, *Vd, *Od;
    cudaGetSymbolAddress((void**)&Qd, g_Q);
    cudaGetSymbolAddress((void**)&Kd, g_K);
    cudaGetSymbolAddress((void**)&Vd, g_V);
    cudaGetSymbolAddress((void**)&Od, g_O);

    cudaFuncSetAttribute(flash_attn, cudaFuncAttributeMaxDynamicSharedMemorySize, 65536);

    // fused Q/K/V projections (z = 0/1/2)
    dim3 gqkv(D_MODEL / 128, M_TOT / 128, 3);
    sgemm_nt_bias<<<gqkv, 256>>>(x, Wq, Wk, Wv, bq, bk, bv, Qd, Kd, Vd);

    // flash attention: one CTA per (64 q-rows, b, h)
    dim3 gattn(SEQ / 64, BATCH * NUM_HEADS);
    flash_attn<<<gattn, 256, 65536>>>(Qd, Kd, Vd, Od);

    // output projection
    dim3 gout(D_MODEL / 128, M_TOT / 128, 1);
    sgemm_nt_bias<<<gout, 256>>>(Od, Wo, Wo, Wo, bo, bo, bo,
                                 (float*)d_out, (float*)d_out, (float*)d_out);
}

// round 3
// speedup vs baseline: 1.2486x; 1.2486x over previous
#include <cuda_runtime.h>
#include <cuda_bf16.h>
#include <stdint.h>
#include <math.h>

#define D_MODEL   1024
#define NUM_HEADS 16
#define BATCH     4
#define SEQ       2048
#define M_TOT     (BATCH * SEQ)   // 8192

// ---------------------------------------------------------------------------
// Scratch (allocation-free: device globals)
// ---------------------------------------------------------------------------
__device__ float g_Q[M_TOT * D_MODEL];
__device__ float g_K[M_TOT * D_MODEL];
__device__ float g_V[M_TOT * D_MODEL];
__device__ float g_O[M_TOT * D_MODEL];
__device__ __nv_bfloat16 g_Ah[M_TOT * D_MODEL];
__device__ __nv_bfloat16 g_Al[M_TOT * D_MODEL];
__device__ __nv_bfloat16 g_Wh[4 * D_MODEL * D_MODEL];
__device__ __nv_bfloat16 g_Wl[4 * D_MODEL * D_MODEL];

// ---------------------------------------------------------------------------
// Helpers: shared addr, cp.async, ldmatrix, mma (all plain sm_100 PTX)
// ---------------------------------------------------------------------------
__device__ __forceinline__ uint32_t smem_u32(const void* p) {
    uint32_t a;
    asm("{ .reg .u64 t; cvta.to.shared.u64 t, %1; cvt.u32.u64 %0, t; }" : "=r"(a) : "l"(p));
    return a;
}
__device__ __forceinline__ void cpa16(uint32_t dst, const void* src) {
    asm volatile("cp.async.cg.shared.global [%0], [%1], 16;" :: "r"(dst), "l"(src));
}
#define CP_COMMIT() asm volatile("cp.async.commit_group;" ::: "memory")

#define LDSM4(r, addr) \
    asm volatile("ldmatrix.sync.aligned.m8n8.x4.shared.b16 {%0,%1,%2,%3}, [%4];" \
        : "=r"((r)[0]), "=r"((r)[1]), "=r"((r)[2]), "=r"((r)[3]) : "r"(addr))

#define MMA_BF16(d, a, b0, b1) \
    asm volatile("mma.sync.aligned.m16n8k16.row.col.f32.bf16.bf16.f32 " \
        "{%0,%1,%2,%3}, {%4,%5,%6,%7}, {%8,%9}, {%0,%1,%2,%3};" \
        : "+f"((d)[0]), "+f"((d)[1]), "+f"((d)[2]), "+f"((d)[3]) \
        : "r"((a)[0]), "r"((a)[1]), "r"((a)[2]), "r"((a)[3]), "r"(b0), "r"(b1))

// ---------------------------------------------------------------------------
// fp32 -> (hi, lo) bf16 split.  4 elems/thread.
// ---------------------------------------------------------------------------
__global__ void cvt_split(const float4* __restrict__ in, uint2* __restrict__ hi,
                          uint2* __restrict__ lo, int n4)
{
    int i = blockIdx.x * blockDim.x + threadIdx.x;
    if (i >= n4) return;
    float4 v = in[i];
    float f[4] = {v.x, v.y, v.z, v.w};
    union { __nv_bfloat16 b[4]; uint2 u; } H, L;
    #pragma unroll
    for (int j = 0; j < 4; j++) {
        __nv_bfloat16 h = __float2bfloat16(f[j]);
        H.b[j] = h;
        L.b[j] = __float2bfloat16(f[j] - __bfloat162float(h));
    }
    hi[i] = H.u;
    lo[i] = L.u;
}

// ---------------------------------------------------------------------------
// HMMA GEMM:  C[m][n] = sum_k A[m][k] * W[n][k] + bias[n]   (NT, fp32 out)
// A,W as bf16 hi/lo; 3-term split (Ah*Wh + Ah*Wl + Al*Wh) in fp32 accum.
// CTA 128x128, BK=32, 3-stage cp.async pipeline, 8 warps (warp tile 64x32).
// SMEM rows padded to 40 bf16 (80B) -> conflict-free ldmatrix.
// blockIdx: x = n-tile, y = m-tile, z = projection select.
// ---------------------------------------------------------------------------
#define STG_BYTES 40960                       // 4 arrays * 128 rows * 80B
#define GEMM_SMEM (3 * STG_BYTES + 128)

__global__ __launch_bounds__(256, 1) void gemm_mma(
    const __nv_bfloat16* __restrict__ Ah, const __nv_bfloat16* __restrict__ Al,
    const __nv_bfloat16* __restrict__ Whb, const __nv_bfloat16* __restrict__ Wlb, int wbase,
    const float* __restrict__ bias0, const float* __restrict__ bias1, const float* __restrict__ bias2,
    float* __restrict__ C0, float* __restrict__ C1, float* __restrict__ C2)
{
    const int z = blockIdx.z;
    const float* bias = (z == 0) ? bias0 : (z == 1) ? bias1 : bias2;
    float* C = (z == 0) ? C0 : (z == 1) ? C1 : C2;
    const __nv_bfloat16* Wh = Whb + (size_t)(wbase + z) * D_MODEL * D_MODEL;
    const __nv_bfloat16* Wl = Wlb + (size_t)(wbase + z) * D_MODEL * D_MODEL;

    const int m0 = blockIdx.y * 128;
    const int n0 = blockIdx.x * 128;
    const int tid  = threadIdx.x;
    const int w    = tid >> 5;
    const int lane = tid & 31;
    const int wm   = w & 1;         // m64 block
    const int wn   = w >> 1;        // n32 block

    extern __shared__ char dyn[];
    const uint32_t sb = (smem_u32(dyn) + 127u) & ~127u;

    // loader: 4 arrays (Ah, Al, Wh, Wl) x 512 chunks of 16B; 256 thr x 2 chunks
    const int r0c = (tid * 2) >> 2;         // row of first chunk (2 chunks adjacent)
    const int c0c = (tid * 2) & 3;          // k-chunk 0..3
    auto load_stage = [&](int stage, int k0) {
        uint32_t base = sb + (uint32_t)stage * STG_BYTES;
        #pragma unroll
        for (int j = 0; j < 2; j++) {
            int id = tid * 2 + j;
            int r = id >> 2, c = id & 3;
            uint32_t off = (uint32_t)(r * 80 + c * 16);
            size_t ga = (size_t)(m0 + r) * D_MODEL + k0 + c * 8;
            size_t gw = (size_t)(n0 + r) * D_MODEL + k0 + c * 8;
            cpa16(base +         off, Ah + ga);
            cpa16(base + 10240 + off, Al + ga);
            cpa16(base + 20480 + off, Wh + gw);
            cpa16(base + 30720 + off, Wl + gw);
        }
        CP_COMMIT();
    };

    load_stage(0, 0);
    load_stage(1, 32);
    load_stage(2, 64);

    float acc[4][4][4];
    #pragma unroll
    for (int i = 0; i < 4; i++)
        #pragma unroll
        for (int j = 0; j < 4; j++)
            #pragma unroll
            for (int q = 0; q < 4; q++) acc[i][j][q] = 0.f;

    const int arow  = lane & 15;            // ldmatrix row select
    const int achk  = (lane >> 4) * 16;     // ldmatrix 16B chunk select

    const int NIT = D_MODEL / 32;           // 32
    for (int it = 0; it < NIT; it++) {
        if (it < NIT - 2)      asm volatile("cp.async.wait_group 2;" ::: "memory");
        else if (it == NIT - 2) asm volatile("cp.async.wait_group 1;" ::: "memory");
        else                    asm volatile("cp.async.wait_group 0;" ::: "memory");
        __syncthreads();

        uint32_t base = sb + (uint32_t)(it % 3) * STG_BYTES;
        uint32_t aoff = base +         (uint32_t)((wm * 64 + arow) * 80) + achk;
        uint32_t boff = base + 20480 + (uint32_t)((wn * 32 + arow) * 80) + achk;

        #pragma unroll
        for (int ks = 0; ks < 2; ks++) {
            uint32_t kadd = (uint32_t)(ks * 32);
            uint32_t a_h[4][4], a_l[4][4], b_h[4], b_l[4], b_h1[4], b_l1[4];
            #pragma unroll
            for (int mb = 0; mb < 4; mb++) {
                LDSM4(a_h[mb], aoff + kadd + (uint32_t)(mb * 16 * 80));
                LDSM4(a_l[mb], aoff + kadd + (uint32_t)(mb * 16 * 80) + 10240u);
            }
            LDSM4(b_h,  boff + kadd);
            LDSM4(b_h1, boff + kadd + (uint32_t)(16 * 80));
            LDSM4(b_l,  boff + kadd + 10240u);
            LDSM4(b_l1, boff + kadd + (uint32_t)(16 * 80) + 10240u);

            #pragma unroll
            for (int mb = 0; mb < 4; mb++) {
                // nf 0,1 from b_h (n 0-15), nf 2,3 from b_h1 (n 16-31)
                MMA_BF16(acc[mb][0], a_h[mb], b_h[0],  b_h[2]);
                MMA_BF16(acc[mb][1], a_h[mb], b_h[1],  b_h[3]);
                MMA_BF16(acc[mb][2], a_h[mb], b_h1[0], b_h1[2]);
                MMA_BF16(acc[mb][3], a_h[mb], b_h1[1], b_h1[3]);
                MMA_BF16(acc[mb][0], a_h[mb], b_l[0],  b_l[2]);
                MMA_BF16(acc[mb][1], a_h[mb], b_l[1],  b_l[3]);
                MMA_BF16(acc[mb][2], a_h[mb], b_l1[0], b_l1[2]);
                MMA_BF16(acc[mb][3], a_h[mb], b_l1[1], b_l1[3]);
                MMA_BF16(acc[mb][0], a_l[mb], b_h[0],  b_h[2]);
                MMA_BF16(acc[mb][1], a_l[mb], b_h[1],  b_h[3]);
                MMA_BF16(acc[mb][2], a_l[mb], b_h1[0], b_h1[2]);
                MMA_BF16(acc[mb][3], a_l[mb], b_h1[1], b_h1[3]);
            }
        }
        __syncthreads();
        if (it + 3 < NIT) load_stage(it % 3, (it + 3) * 32);
    }

    // epilogue: accum layout m16n8: c0,c1 row=lane/4 cols (lane%4)*2,+1; c2,c3 row+8
    #pragma unroll
    for (int mb = 0; mb < 4; mb++) {
        int r0 = m0 + wm * 64 + mb * 16 + (lane >> 2);
        float* c0p = C + (size_t)r0 * D_MODEL;
        float* c1p = c0p + 8 * D_MODEL;
        #pragma unroll
        for (int nf = 0; nf < 4; nf++) {
            int col = n0 + wn * 32 + nf * 8 + (lane & 3) * 2;
            float b0 = bias[col], b1 = bias[col + 1];
            float2 v0 = make_float2(acc[mb][nf][0] + b0, acc[mb][nf][1] + b1);
            float2 v1 = make_float2(acc[mb][nf][2] + b0, acc[mb][nf][3] + b1);
            *(float2*)(c0p + col) = v0;
            *(float2*)(c1p + col) = v1;
        }
    }
}

// ---------------------------------------------------------------------------
// Flash attention, fp32 SIMT (unchanged from R1 — known correct)
// ---------------------------------------------------------------------------
__global__ __launch_bounds__(256) void flash_attn(
    const float* __restrict__ Q, const float* __restrict__ K,
    const float* __restrict__ V, float* __restrict__ O)
{
    extern __shared__ float sm[];
    float* Qs = sm;            // [d][r] transposed, 64x64
    float* Ks = sm + 4096;     // [d][c] transposed
    float* Vs = sm + 8192;     // [c][d] natural
    float* Ps = sm + 12288;    // [c][r] transposed

    const int tid = threadIdx.x;
    const int tx  = tid & 15;
    const int ty  = tid >> 4;
    const int b   = blockIdx.y >> 4;
    const int h   = blockIdx.y & 15;
    const int q0  = blockIdx.x * 64;

    const int lr  = tid >> 2;
    const int ld0 = (tid & 3) * 16;

    {
        const float* qp = Q + (size_t)(b * SEQ + q0 + lr) * D_MODEL + h * 64 + ld0;
        #pragma unroll
        for (int i = 0; i < 4; i++) {
            float4 v = *(const float4*)(qp + i * 4);
            int d = ld0 + i * 4;
            Qs[(d + 0) * 64 + lr] = v.x * 0.125f;
            Qs[(d + 1) * 64 + lr] = v.y * 0.125f;
            Qs[(d + 2) * 64 + lr] = v.z * 0.125f;
            Qs[(d + 3) * 64 + lr] = v.w * 0.125f;
        }
    }

    float o[4][4];
    float mrun[4], lrun[4];
    #pragma unroll
    for (int i = 0; i < 4; i++) {
        mrun[i] = -1e30f;
        lrun[i] = 0.f;
        #pragma unroll
        for (int j = 0; j < 4; j++) o[i][j] = 0.f;
    }

    for (int kt = 0; kt < SEQ / 64; kt++) {
        const int c0 = kt * 64;
        {
            const float* kp = K + (size_t)(b * SEQ + c0 + lr) * D_MODEL + h * 64 + ld0;
            const float* vp = V + (size_t)(b * SEQ + c0 + lr) * D_MODEL + h * 64 + ld0;
            #pragma unroll
            for (int i = 0; i < 4; i++) {
                int d = ld0 + i * 4;
                float4 kv = *(const float4*)(kp + i * 4);
                Ks[(d + 0) * 64 + lr] = kv.x;
                Ks[(d + 1) * 64 + lr] = kv.y;
                Ks[(d + 2) * 64 + lr] = kv.z;
                Ks[(d + 3) * 64 + lr] = kv.w;
                float4 vv = *(const float4*)(vp + i * 4);
                *(float4*)&Vs[lr * 64 + d] = vv;
            }
        }
        __syncthreads();

        float s[4][4];
        #pragma unroll
        for (int i = 0; i < 4; i++)
            #pragma unroll
            for (int j = 0; j < 4; j++) s[i][j] = 0.f;
        #pragma unroll 8
        for (int d = 0; d < 64; d++) {
            float4 a  = *(const float4*)&Qs[d * 64 + ty * 4];
            float4 bb = *(const float4*)&Ks[d * 64 + tx * 4];
            float av[4] = {a.x, a.y, a.z, a.w};
            float bv[4] = {bb.x, bb.y, bb.z, bb.w};
            #pragma unroll
            for (int i = 0; i < 4; i++)
                #pragma unroll
                for (int j = 0; j < 4; j++)
                    s[i][j] = fmaf(av[i], bv[j], s[i][j]);
        }

        #pragma unroll
        for (int i = 0; i < 4; i++) {
            float mloc = fmaxf(fmaxf(s[i][0], s[i][1]), fmaxf(s[i][2], s[i][3]));
            #pragma unroll
            for (int off = 1; off < 16; off <<= 1)
                mloc = fmaxf(mloc, __shfl_xor_sync(0xffffffffu, mloc, off));
            float mnew = fmaxf(mrun[i], mloc);
            float corr = __expf(mrun[i] - mnew);
            float lloc = 0.f;
            #pragma unroll
            for (int j = 0; j < 4; j++) {
                s[i][j] = __expf(s[i][j] - mnew);
                lloc += s[i][j];
            }
            #pragma unroll
            for (int off = 1; off < 16; off <<= 1)
                lloc += __shfl_xor_sync(0xffffffffu, lloc, off);
            lrun[i] = lrun[i] * corr + lloc;
            mrun[i] = mnew;
            #pragma unroll
            for (int j = 0; j < 4; j++) {
                o[i][j] *= corr;
                Ps[(tx * 4 + j) * 64 + ty * 4 + i] = s[i][j];
            }
        }
        __syncthreads();

        #pragma unroll 8
        for (int c = 0; c < 64; c++) {
            float4 a  = *(const float4*)&Ps[c * 64 + ty * 4];
            float4 bb = *(const float4*)&Vs[c * 64 + tx * 4];
            float av[4] = {a.x, a.y, a.z, a.w};
            float bv[4] = {bb.x, bb.y, bb.z, bb.w};
            #pragma unroll
            for (int i = 0; i < 4; i++)
                #pragma unroll
                for (int j = 0; j < 4; j++)
                    o[i][j] = fmaf(av[i], bv[j], o[i][j]);
        }
        __syncthreads();
    }

    #pragma unroll
    for (int i = 0; i < 4; i++) {
        float inv = 1.f / lrun[i];
        int srow = q0 + ty * 4 + i;
        float4 r = make_float4(o[i][0] * inv, o[i][1] * inv,
                               o[i][2] * inv, o[i][3] * inv);
        *(float4*)&O[(size_t)(b * SEQ + srow) * D_MODEL + h * 64 + tx * 4] = r;
    }
}

// ---------------------------------------------------------------------------
extern "C" void kernel_launch(void* const* d_in, const int* in_sizes, int n_in,
                              void* d_out, int out_size)
{
    const float* x  = (const float*)d_in[0];
    const float* Wq = (const float*)d_in[1];
    const float* bq = (const float*)d_in[2];
    const float* Wk = (const float*)d_in[3];
    const float* bk = (const float*)d_in[4];
    const float* Wv = (const float*)d_in[5];
    const float* bv = (const float*)d_in[6];
    const float* Wo = (const float*)d_in[7];
    const float* bo = (const float*)d_in[8];

    float *Qd, *Kd, *Vd, *Od;
    __nv_bfloat16 *Ah, *Al, *Wh, *Wl;
    cudaGetSymbolAddress((void**)&Qd, g_Q);
    cudaGetSymbolAddress((void**)&Kd, g_K);
    cudaGetSymbolAddress((void**)&Vd, g_V);
    cudaGetSymbolAddress((void**)&Od, g_O);
    cudaGetSymbolAddress((void**)&Ah, g_Ah);
    cudaGetSymbolAddress((void**)&Al, g_Al);
    cudaGetSymbolAddress((void**)&Wh, g_Wh);
    cudaGetSymbolAddress((void**)&Wl, g_Wl);

    cudaFuncSetAttribute(gemm_mma, cudaFuncAttributeMaxDynamicSharedMemorySize, GEMM_SMEM);
    cudaFuncSetAttribute(flash_attn, cudaFuncAttributeMaxDynamicSharedMemorySize, 65536);

    const int NW4 = D_MODEL * D_MODEL / 4;   // 262144 float4 per weight
    cvt_split<<<NW4 / 256, 256>>>((const float4*)Wq, (uint2*)(Wh + 0 * 1048576), (uint2*)(Wl + 0 * 1048576), NW4);
    cvt_split<<<NW4 / 256, 256>>>((const float4*)Wk, (uint2*)(Wh + 1 * 1048576), (uint2*)(Wl + 1 * 1048576), NW4);
    cvt_split<<<NW4 / 256, 256>>>((const float4*)Wv, (uint2*)(Wh + 2 * 1048576), (uint2*)(Wl + 2 * 1048576), NW4);
    cvt_split<<<NW4 / 256, 256>>>((const float4*)Wo, (uint2*)(Wh + 3 * 1048576), (uint2*)(Wl + 3 * 1048576), NW4);
    const int NX4 = M_TOT * D_MODEL / 4;     // 2097152
    cvt_split<<<NX4 / 256, 256>>>((const float4*)x, (uint2*)Ah, (uint2*)Al, NX4);

    // Q/K/V projections (z = 0/1/2)
    dim3 gqkv(D_MODEL / 128, M_TOT / 128, 3);
    gemm_mma<<<gqkv, 256, GEMM_SMEM>>>(Ah, Al, Wh, Wl, 0, bq, bk, bv, Qd, Kd, Vd);

    // attention
    dim3 gattn(SEQ / 64, BATCH * NUM_HEADS);
    flash_attn<<<gattn, 256, 65536>>>(Qd, Kd, Vd, Od);

    // attn-output split (reuse Ah/Al), then O projection -> d_out
    cvt_split<<<NX4 / 256, 256>>>((const float4*)Od, (uint2*)Ah, (uint2*)Al, NX4);
    dim3 gout(D_MODEL / 128, M_TOT / 128, 1);
    gemm_mma<<<gout, 256, GEMM_SMEM>>>(Ah, Al, Wh, Wl, 3, bo, bo, bo,
                                       (float*)d_out, (float*)d_out, (float*)d_out);
}

// round 4
// speedup vs baseline: 2.7998x; 2.2424x over previous
#include <cuda_runtime.h>
#include <cuda_bf16.h>
#include <stdint.h>
#include <math.h>

#define D_MODEL   1024
#define NUM_HEADS 16
#define BATCH     4
#define SEQ       2048
#define M_TOT     (BATCH * SEQ)   // 8192

typedef __nv_bfloat16 bf16;

// ---------------------------------------------------------------------------
// Scratch (allocation-free: device globals)
// ---------------------------------------------------------------------------
__device__ bf16 g_Ah[M_TOT * D_MODEL];
__device__ bf16 g_Al[M_TOT * D_MODEL];
__device__ bf16 g_Wh[4 * D_MODEL * D_MODEL];
__device__ bf16 g_Wl[4 * D_MODEL * D_MODEL];
__device__ bf16 g_Qh[M_TOT * D_MODEL];
__device__ bf16 g_Ql[M_TOT * D_MODEL];
__device__ bf16 g_Kh[M_TOT * D_MODEL];
__device__ bf16 g_Kl[M_TOT * D_MODEL];
__device__ bf16 g_Vh[M_TOT * D_MODEL];
__device__ bf16 g_Vl[M_TOT * D_MODEL];

// ---------------------------------------------------------------------------
// Helpers (plain sm_100 PTX: cp.async, ldmatrix, mma.sync)
// ---------------------------------------------------------------------------
__device__ __forceinline__ uint32_t smem_u32(const void* p) {
    uint32_t a;
    asm("{ .reg .u64 t; cvta.to.shared.u64 t, %1; cvt.u32.u64 %0, t; }" : "=r"(a) : "l"(p));
    return a;
}
__device__ __forceinline__ void cpa16(uint32_t dst, const void* src) {
    asm volatile("cp.async.cg.shared.global [%0], [%1], 16;" :: "r"(dst), "l"(src));
}
#define CP_COMMIT() asm volatile("cp.async.commit_group;" ::: "memory")

#define LDSM4(r, addr) \
    asm volatile("ldmatrix.sync.aligned.m8n8.x4.shared.b16 {%0,%1,%2,%3}, [%4];" \
        : "=r"((r)[0]), "=r"((r)[1]), "=r"((r)[2]), "=r"((r)[3]) : "r"(addr))
#define LDSMT4(r, addr) \
    asm volatile("ldmatrix.sync.aligned.m8n8.x4.trans.shared.b16 {%0,%1,%2,%3}, [%4];" \
        : "=r"((r)[0]), "=r"((r)[1]), "=r"((r)[2]), "=r"((r)[3]) : "r"(addr))

#define MMA_BF16(d, a, b0, b1) \
    asm volatile("mma.sync.aligned.m16n8k16.row.col.f32.bf16.bf16.f32 " \
        "{%0,%1,%2,%3}, {%4,%5,%6,%7}, {%8,%9}, {%0,%1,%2,%3};" \
        : "+f"((d)[0]), "+f"((d)[1]), "+f"((d)[2]), "+f"((d)[3]) \
        : "r"((a)[0]), "r"((a)[1]), "r"((a)[2]), "r"((a)[3]), "r"(b0), "r"(b1))

// pack two floats -> {bf16 hi pair, bf16 residual pair}
__device__ __forceinline__ void split2(float a, float b, uint32_t& h, uint32_t& l) {
    __nv_bfloat162 hh = __floats2bfloat162_rn(a, b);
    float2 hf = __bfloat1622float2(hh);
    __nv_bfloat162 ll = __floats2bfloat162_rn(a - hf.x, b - hf.y);
    h = *(uint32_t*)&hh;
    l = *(uint32_t*)&ll;
}

// ---------------------------------------------------------------------------
// fp32 -> (hi, lo) bf16 split stream kernel
// ---------------------------------------------------------------------------
__global__ void cvt_split(const float4* __restrict__ in, uint2* __restrict__ hi,
                          uint2* __restrict__ lo, int n4)
{
    int i = blockIdx.x * blockDim.x + threadIdx.x;
    if (i >= n4) return;
    float4 v = in[i];
    float f[4] = {v.x, v.y, v.z, v.w};
    union { bf16 b[4]; uint2 u; } H, L;
    #pragma unroll
    for (int j = 0; j < 4; j++) {
        bf16 h = __float2bfloat16(f[j]);
        H.b[j] = h;
        L.b[j] = __float2bfloat16(f[j] - __bfloat162float(h));
    }
    hi[i] = H.u;
    lo[i] = L.u;
}

// ---------------------------------------------------------------------------
// HMMA GEMM:  C = A @ W^T + bias   (A,W bf16 hi/lo, 3-term split, fp32 accum)
// CTA 128x128, BK=32, 3-stage cp.async, 8 warps (warp tile 64x32).
// mode 0: fp32 out (+bias).  mode 1: (acc+bias)*scale split to bf16 hi/lo.
// ---------------------------------------------------------------------------
#define STG_BYTES 40960
#define GEMM_SMEM (3 * STG_BYTES + 128)

__global__ __launch_bounds__(256, 1) void gemm_mma(
    const bf16* __restrict__ Ah, const bf16* __restrict__ Al,
    const bf16* __restrict__ Whb, const bf16* __restrict__ Wlb, int wbase,
    const float* __restrict__ bias0, const float* __restrict__ bias1, const float* __restrict__ bias2,
    float* __restrict__ C0, int mode,
    bf16* H0, bf16* L0, bf16* H1, bf16* L1, bf16* H2, bf16* L2,
    float s0, float s1, float s2)
{
    const int z = blockIdx.z;
    const float* bias = (z == 0) ? bias0 : (z == 1) ? bias1 : bias2;
    const bf16* Wh = Whb + (size_t)(wbase + z) * D_MODEL * D_MODEL;
    const bf16* Wl = Wlb + (size_t)(wbase + z) * D_MODEL * D_MODEL;

    const int m0 = blockIdx.y * 128;
    const int n0 = blockIdx.x * 128;
    const int tid  = threadIdx.x;
    const int w    = tid >> 5;
    const int lane = tid & 31;
    const int wm   = w & 1;
    const int wn   = w >> 1;

    extern __shared__ char dyn[];
    const uint32_t sb = (smem_u32(dyn) + 127u) & ~127u;

    auto load_stage = [&](int stage, int k0) {
        uint32_t base = sb + (uint32_t)stage * STG_BYTES;
        #pragma unroll
        for (int j = 0; j < 2; j++) {
            int id = tid * 2 + j;
            int r = id >> 2, c = id & 3;
            uint32_t off = (uint32_t)(r * 80 + c * 16);
            size_t ga = (size_t)(m0 + r) * D_MODEL + k0 + c * 8;
            size_t gw = (size_t)(n0 + r) * D_MODEL + k0 + c * 8;
            cpa16(base +         off, Ah + ga);
            cpa16(base + 10240 + off, Al + ga);
            cpa16(base + 20480 + off, Wh + gw);
            cpa16(base + 30720 + off, Wl + gw);
        }
        CP_COMMIT();
    };

    load_stage(0, 0);
    load_stage(1, 32);
    load_stage(2, 64);

    float acc[4][4][4];
    #pragma unroll
    for (int i = 0; i < 4; i++)
        #pragma unroll
        for (int j = 0; j < 4; j++)
            #pragma unroll
            for (int q = 0; q < 4; q++) acc[i][j][q] = 0.f;

    const int arow = lane & 15;
    const int achk = (lane >> 4) * 16;

    const int NIT = D_MODEL / 32;
    for (int it = 0; it < NIT; it++) {
        if (it < NIT - 2)       asm volatile("cp.async.wait_group 2;" ::: "memory");
        else if (it == NIT - 2) asm volatile("cp.async.wait_group 1;" ::: "memory");
        else                    asm volatile("cp.async.wait_group 0;" ::: "memory");
        __syncthreads();

        uint32_t base = sb + (uint32_t)(it % 3) * STG_BYTES;
        uint32_t aoff = base +         (uint32_t)((wm * 64 + arow) * 80) + achk;
        uint32_t boff = base + 20480 + (uint32_t)((wn * 32 + arow) * 80) + achk;

        #pragma unroll
        for (int ks = 0; ks < 2; ks++) {
            uint32_t kadd = (uint32_t)(ks * 32);
            uint32_t a_h[4][4], a_l[4][4], b_h[4], b_l[4], b_h1[4], b_l1[4];
            #pragma unroll
            for (int mb = 0; mb < 4; mb++) {
                LDSM4(a_h[mb], aoff + kadd + (uint32_t)(mb * 16 * 80));
                LDSM4(a_l[mb], aoff + kadd + (uint32_t)(mb * 16 * 80) + 10240u);
            }
            LDSM4(b_h,  boff + kadd);
            LDSM4(b_h1, boff + kadd + (uint32_t)(16 * 80));
            LDSM4(b_l,  boff + kadd + 10240u);
            LDSM4(b_l1, boff + kadd + (uint32_t)(16 * 80) + 10240u);

            // term-major ordering: same-acc reuse distance = 16 MMAs
            #pragma unroll
            for (int mb = 0; mb < 4; mb++) {
                MMA_BF16(acc[mb][0], a_h[mb], b_h[0],  b_h[2]);
                MMA_BF16(acc[mb][1], a_h[mb], b_h[1],  b_h[3]);
                MMA_BF16(acc[mb][2], a_h[mb], b_h1[0], b_h1[2]);
                MMA_BF16(acc[mb][3], a_h[mb], b_h1[1], b_h1[3]);
            }
            #pragma unroll
            for (int mb = 0; mb < 4; mb++) {
                MMA_BF16(acc[mb][0], a_h[mb], b_l[0],  b_l[2]);
                MMA_BF16(acc[mb][1], a_h[mb], b_l[1],  b_l[3]);
                MMA_BF16(acc[mb][2], a_h[mb], b_l1[0], b_l1[2]);
                MMA_BF16(acc[mb][3], a_h[mb], b_l1[1], b_l1[3]);
            }
            #pragma unroll
            for (int mb = 0; mb < 4; mb++) {
                MMA_BF16(acc[mb][0], a_l[mb], b_h[0],  b_h[2]);
                MMA_BF16(acc[mb][1], a_l[mb], b_h[1],  b_h[3]);
                MMA_BF16(acc[mb][2], a_l[mb], b_h1[0], b_h1[2]);
                MMA_BF16(acc[mb][3], a_l[mb], b_h1[1], b_h1[3]);
            }
        }
        __syncthreads();
        if (it + 3 < NIT) load_stage(it % 3, (it + 3) * 32);
    }

    if (mode == 0) {
        #pragma unroll
        for (int mb = 0; mb < 4; mb++) {
            int r0 = m0 + wm * 64 + mb * 16 + (lane >> 2);
            float* c0p = C0 + (size_t)r0 * D_MODEL;
            float* c1p = c0p + 8 * D_MODEL;
            #pragma unroll
            for (int nf = 0; nf < 4; nf++) {
                int col = n0 + wn * 32 + nf * 8 + (lane & 3) * 2;
                float b0 = bias[col], b1 = bias[col + 1];
                *(float2*)(c0p + col) = make_float2(acc[mb][nf][0] + b0, acc[mb][nf][1] + b1);
                *(float2*)(c1p + col) = make_float2(acc[mb][nf][2] + b0, acc[mb][nf][3] + b1);
            }
        }
    } else {
        bf16* H = (z == 0) ? H0 : (z == 1) ? H1 : H2;
        bf16* L = (z == 0) ? L0 : (z == 1) ? L1 : L2;
        float scl = (z == 0) ? s0 : (z == 1) ? s1 : s2;
        #pragma unroll
        for (int mb = 0; mb < 4; mb++) {
            int r0 = m0 + wm * 64 + mb * 16 + (lane >> 2);
            #pragma unroll
            for (int nf = 0; nf < 4; nf++) {
                int col = n0 + wn * 32 + nf * 8 + (lane & 3) * 2;
                float b0 = bias[col], b1 = bias[col + 1];
                uint32_t h0, l0, h1, l1;
                split2((acc[mb][nf][0] + b0) * scl, (acc[mb][nf][1] + b1) * scl, h0, l0);
                split2((acc[mb][nf][2] + b0) * scl, (acc[mb][nf][3] + b1) * scl, h1, l1);
                *(uint32_t*)(H + (size_t)r0 * D_MODEL + col)       = h0;
                *(uint32_t*)(L + (size_t)r0 * D_MODEL + col)       = l0;
                *(uint32_t*)(H + (size_t)(r0 + 8) * D_MODEL + col) = h1;
                *(uint32_t*)(L + (size_t)(r0 + 8) * D_MODEL + col) = l1;
            }
        }
    }
}

// ---------------------------------------------------------------------------
// Flash attention on HMMA. CTA = 128 q-rows of one (b,h). KV tiles of 64 cols
// double-buffered via cp.async. Warp = 16 full rows -> softmax is quad-shuffle
// only. S = Qh·Kh + Qh·Kl + Ql·Kh; O += Ph·Vh + Ph·Vl + Pl·Vh. P fragments
// are re-used directly as A operands (C-frag layout == A-frag layout).
// V consumed via ldmatrix.trans. Output written as bf16 hi/lo for O-proj.
// ---------------------------------------------------------------------------
#define SD        144                 // smem row stride bytes (64 bf16 + pad)
#define QH_S      0
#define QL_S      18432
#define STAGE0    36864
#define STAGE_SZ  36864               // Kh,Kl,Vh,Vl each 64*144
#define AKH       0
#define AKL       9216
#define AVH       18432
#define AVL       27648
#define ATTN_SMEM (STAGE0 + 2 * STAGE_SZ)   // 110592

__global__ __launch_bounds__(256, 1) void attn_mma(
    const bf16* __restrict__ Qh, const bf16* __restrict__ Ql,
    const bf16* __restrict__ Kh, const bf16* __restrict__ Kl,
    const bf16* __restrict__ Vh, const bf16* __restrict__ Vl,
    bf16* __restrict__ Oh, bf16* __restrict__ Ol)
{
    extern __shared__ char dyn[];
    const uint32_t sb = (smem_u32(dyn) + 127u) & ~127u;

    const int tid  = threadIdx.x;
    const int w    = tid >> 5;
    const int lane = tid & 31;
    const int b    = blockIdx.y >> 4;
    const int h    = blockIdx.y & 15;
    const int q0   = blockIdx.x * 128;

    // ---- Q tile load (once) ----
    #pragma unroll
    for (int t = 0; t < 4; t++) {
        int i = tid + t * 256;
        int row = i >> 3, ch = i & 7;
        size_t off = (size_t)(b * SEQ + q0 + row) * D_MODEL + h * 64 + ch * 8;
        cpa16(sb + QH_S + (uint32_t)(row * SD + ch * 16), Qh + off);
        cpa16(sb + QL_S + (uint32_t)(row * SD + ch * 16), Ql + off);
    }
    CP_COMMIT();

    auto load_kv = [&](int stage, int c0) {
        uint32_t base = sb + STAGE0 + (uint32_t)stage * STAGE_SZ;
        #pragma unroll
        for (int t = 0; t < 8; t++) {
            int i = tid + t * 256;
            int arr = i >> 9, r = (i >> 3) & 63, ch = i & 7;
            size_t off = (size_t)(b * SEQ + c0 + r) * D_MODEL + h * 64 + ch * 8;
            const bf16* src = (arr == 0) ? Kh : (arr == 1) ? Kl : (arr == 2) ? Vh : Vl;
            cpa16(base + (uint32_t)(arr * 9216 + r * SD + ch * 16), src + off);
        }
        CP_COMMIT();
    };
    load_kv(0, 0);
    load_kv(1, 64);

    // ---- Q fragments (kept in registers for whole loop) ----
    asm volatile("cp.async.wait_group 2;" ::: "memory");
    __syncthreads();
    uint32_t qh[4][4], ql[4][4];
    {
        uint32_t qa = sb + (uint32_t)((w * 16 + (lane & 15)) * SD) + (uint32_t)((lane >> 4) * 16);
        #pragma unroll
        for (int kf = 0; kf < 4; kf++) {
            LDSM4(qh[kf], qa + QH_S + (uint32_t)(kf * 32));
            LDSM4(ql[kf], qa + QL_S + (uint32_t)(kf * 32));
        }
    }

    float oacc[8][4];
    #pragma unroll
    for (int i = 0; i < 8; i++)
        #pragma unroll
        for (int j = 0; j < 4; j++) oacc[i][j] = 0.f;
    float mrun[2] = {-1e30f, -1e30f};
    float lrun[2] = {0.f, 0.f};

    const uint32_t krow = (uint32_t)((lane & 15) * SD) + (uint32_t)((lane >> 4) * 16);
    const uint32_t vrow = (uint32_t)((((lane >> 3) & 1) * 8 + (lane & 7)) * SD)
                        + (uint32_t)(((lane >> 4) & 1) * 16);   // +8 n -> +16 bytes

    const int NT = SEQ / 64;   // 32
    for (int kt = 0; kt < NT; kt++) {
        if (kt < NT - 1) asm volatile("cp.async.wait_group 1;" ::: "memory");
        else             asm volatile("cp.async.wait_group 0;" ::: "memory");
        __syncthreads();
        uint32_t buf = sb + STAGE0 + (uint32_t)(kt & 1) * STAGE_SZ;

        // ---- S = Q K^T (3-term) ----
        float sacc[8][4];
        #pragma unroll
        for (int i = 0; i < 8; i++)
            #pragma unroll
            for (int j = 0; j < 4; j++) sacc[i][j] = 0.f;

        #pragma unroll
        for (int kf = 0; kf < 4; kf++) {
            uint32_t bh[4][4], bl[4][4];
            #pragma unroll
            for (int g = 0; g < 4; g++) {
                uint32_t ka = buf + (uint32_t)(g * 16 * SD) + krow + (uint32_t)(kf * 32);
                LDSM4(bh[g], ka + AKH);
                LDSM4(bl[g], ka + AKL);
            }
            #pragma unroll
            for (int g = 0; g < 4; g++) {
                MMA_BF16(sacc[2 * g],     qh[kf], bh[g][0], bh[g][2]);
                MMA_BF16(sacc[2 * g + 1], qh[kf], bh[g][1], bh[g][3]);
            }
            #pragma unroll
            for (int g = 0; g < 4; g++) {
                MMA_BF16(sacc[2 * g],     qh[kf], bl[g][0], bl[g][2]);
                MMA_BF16(sacc[2 * g + 1], qh[kf], bl[g][1], bl[g][3]);
            }
            #pragma unroll
            for (int g = 0; g < 4; g++) {
                MMA_BF16(sacc[2 * g],     ql[kf], bh[g][0], bh[g][2]);
                MMA_BF16(sacc[2 * g + 1], ql[kf], bh[g][1], bh[g][3]);
            }
        }

        // ---- online softmax (2 row-slots per thread) ----
        #pragma unroll
        for (int slot = 0; slot < 2; slot++) {
            const int o0 = slot * 2;
            float ml = -1e30f;
            #pragma unroll
            for (int nf = 0; nf < 8; nf++)
                ml = fmaxf(ml, fmaxf(sacc[nf][o0], sacc[nf][o0 + 1]));
            ml = fmaxf(ml, __shfl_xor_sync(0xffffffffu, ml, 1));
            ml = fmaxf(ml, __shfl_xor_sync(0xffffffffu, ml, 2));
            float mnew = fmaxf(mrun[slot], ml);
            float corr = __expf(mrun[slot] - mnew);
            float ls = 0.f;
            #pragma unroll
            for (int nf = 0; nf < 8; nf++) {
                sacc[nf][o0]     = __expf(sacc[nf][o0]     - mnew);
                sacc[nf][o0 + 1] = __expf(sacc[nf][o0 + 1] - mnew);
                ls += sacc[nf][o0] + sacc[nf][o0 + 1];
            }
            ls += __shfl_xor_sync(0xffffffffu, ls, 1);
            ls += __shfl_xor_sync(0xffffffffu, ls, 2);
            lrun[slot] = lrun[slot] * corr + ls;
            mrun[slot] = mnew;
            #pragma unroll
            for (int nf = 0; nf < 8; nf++) {
                oacc[nf][o0]     *= corr;
                oacc[nf][o0 + 1] *= corr;
            }
        }

        // ---- O += P V (3-term); P fragments straight from sacc ----
        #pragma unroll
        for (int kf2 = 0; kf2 < 4; kf2++) {
            float* sA = sacc[2 * kf2];
            float* sB = sacc[2 * kf2 + 1];
            uint32_t ph[4], pl[4];
            split2(sA[0], sA[1], ph[0], pl[0]);
            split2(sA[2], sA[3], ph[1], pl[1]);
            split2(sB[0], sB[1], ph[2], pl[2]);
            split2(sB[2], sB[3], ph[3], pl[3]);

            uint32_t vhr[4][4], vlr[4][4];
            #pragma unroll
            for (int g = 0; g < 4; g++) {
                uint32_t va = buf + (uint32_t)(kf2 * 16 * SD) + vrow + (uint32_t)(g * 32);
                LDSMT4(vhr[g], va + AVH);
                LDSMT4(vlr[g], va + AVL);
            }
            #pragma unroll
            for (int g = 0; g < 4; g++) {
                MMA_BF16(oacc[2 * g],     ph, vhr[g][0], vhr[g][1]);
                MMA_BF16(oacc[2 * g + 1], ph, vhr[g][2], vhr[g][3]);
            }
            #pragma unroll
            for (int g = 0; g < 4; g++) {
                MMA_BF16(oacc[2 * g],     ph, vlr[g][0], vlr[g][1]);
                MMA_BF16(oacc[2 * g + 1], ph, vlr[g][2], vlr[g][3]);
            }
            #pragma unroll
            for (int g = 0; g < 4; g++) {
                MMA_BF16(oacc[2 * g],     pl, vhr[g][0], vhr[g][1]);
                MMA_BF16(oacc[2 * g + 1], pl, vhr[g][2], vhr[g][3]);
            }
        }
        __syncthreads();
        if (kt + 2 < NT) load_kv(kt & 1, (kt + 2) * 64);
    }

    // ---- epilogue: normalize + hi/lo split to model layout ----
    #pragma unroll
    for (int slot = 0; slot < 2; slot++) {
        float inv = 1.f / lrun[slot];
        size_t grow = (size_t)(b * SEQ + q0 + w * 16 + (lane >> 2) + slot * 8);
        #pragma unroll
        for (int nf = 0; nf < 8; nf++) {
            int col = h * 64 + nf * 8 + (lane & 3) * 2;
            uint32_t hw, lw;
            split2(oacc[nf][slot * 2] * inv, oacc[nf][slot * 2 + 1] * inv, hw, lw);
            *(uint32_t*)(Oh + grow * D_MODEL + col) = hw;
            *(uint32_t*)(Ol + grow * D_MODEL + col) = lw;
        }
    }
}

// ---------------------------------------------------------------------------
extern "C" void kernel_launch(void* const* d_in, const int* in_sizes, int n_in,
                              void* d_out, int out_size)
{
    const float* x  = (const float*)d_in[0];
    const float* Wq = (const float*)d_in[1];
    const float* bq = (const float*)d_in[2];
    const float* Wk = (const float*)d_in[3];
    const float* bk = (const float*)d_in[4];
    const float* Wv = (const float*)d_in[5];
    const float* bv = (const float*)d_in[6];
    const float* Wo = (const float*)d_in[7];
    const float* bo = (const float*)d_in[8];

    bf16 *Ah, *Al, *Wh, *Wl, *Qh, *Ql, *Kh, *Kl, *Vh, *Vl;
    cudaGetSymbolAddress((void**)&Ah, g_Ah);
    cudaGetSymbolAddress((void**)&Al, g_Al);
    cudaGetSymbolAddress((void**)&Wh, g_Wh);
    cudaGetSymbolAddress((void**)&Wl, g_Wl);
    cudaGetSymbolAddress((void**)&Qh, g_Qh);
    cudaGetSymbolAddress((void**)&Ql, g_Ql);
    cudaGetSymbolAddress((void**)&Kh, g_Kh);
    cudaGetSymbolAddress((void**)&Kl, g_Kl);
    cudaGetSymbolAddress((void**)&Vh, g_Vh);
    cudaGetSymbolAddress((void**)&Vl, g_Vl);

    cudaFuncSetAttribute(gemm_mma, cudaFuncAttributeMaxDynamicSharedMemorySize, GEMM_SMEM);
    cudaFuncSetAttribute(attn_mma, cudaFuncAttributeMaxDynamicSharedMemorySize, ATTN_SMEM);

    const int NW4 = D_MODEL * D_MODEL / 4;
    cvt_split<<<NW4 / 256, 256>>>((const float4*)Wq, (uint2*)(Wh + 0 * 1048576), (uint2*)(Wl + 0 * 1048576), NW4);
    cvt_split<<<NW4 / 256, 256>>>((const float4*)Wk, (uint2*)(Wh + 1 * 1048576), (uint2*)(Wl + 1 * 1048576), NW4);
    cvt_split<<<NW4 / 256, 256>>>((const float4*)Wv, (uint2*)(Wh + 2 * 1048576), (uint2*)(Wl + 2 * 1048576), NW4);
    cvt_split<<<NW4 / 256, 256>>>((const float4*)Wo, (uint2*)(Wh + 3 * 1048576), (uint2*)(Wl + 3 * 1048576), NW4);
    const int NX4 = M_TOT * D_MODEL / 4;
    cvt_split<<<NX4 / 256, 256>>>((const float4*)x, (uint2*)Ah, (uint2*)Al, NX4);

    // Q/K/V projections -> bf16 hi/lo directly (Q pre-scaled by 1/8)
    dim3 gqkv(D_MODEL / 128, M_TOT / 128, 3);
    gemm_mma<<<gqkv, 256, GEMM_SMEM>>>(Ah, Al, Wh, Wl, 0, bq, bk, bv,
                                       nullptr, 1, Qh, Ql, Kh, Kl, Vh, Vl,
                                       0.125f, 1.f, 1.f);

    // attention -> bf16 hi/lo into Ah/Al (x-split no longer needed)
    dim3 gattn(SEQ / 128, BATCH * NUM_HEADS);
    attn_mma<<<gattn, 256, ATTN_SMEM>>>(Qh, Ql, Kh, Kl, Vh, Vl, Ah, Al);

    // output projection -> fp32 d_out
    dim3 gout(D_MODEL / 128, M_TOT / 128, 1);
    gemm_mma<<<gout, 256, GEMM_SMEM>>>(Ah, Al, Wh, Wl, 3, bo, bo, bo,
                                       (float*)d_out, 0,
                                       nullptr, nullptr, nullptr, nullptr, nullptr, nullptr,
                                       1.f, 1.f, 1.f);
}

// round 5
// speedup vs baseline: 4.3532x; 1.5548x over previous
#include <cuda_runtime.h>
#include <cuda_fp16.h>
#include <stdint.h>
#include <math.h>

#define D_MODEL   1024
#define NUM_HEADS 16
#define BATCH     4
#define SEQ       2048
#define M_TOT     (BATCH * SEQ)   // 8192

typedef __half h16;

// ---------------------------------------------------------------------------
// Scratch (allocation-free: device globals)
// ---------------------------------------------------------------------------
__device__ h16 g_Ah[M_TOT * D_MODEL];        // A-operand hi (x, then attn out)
__device__ h16 g_Al[M_TOT * D_MODEL];        // A-operand lo
__device__ h16 g_Wh[4 * D_MODEL * D_MODEL];  // weights, single fp16
__device__ h16 g_Qh[M_TOT * D_MODEL];
__device__ h16 g_Ql[M_TOT * D_MODEL];
__device__ h16 g_Kh[M_TOT * D_MODEL];        // K single fp16
__device__ h16 g_Vh[M_TOT * D_MODEL];        // V single fp16

// ---------------------------------------------------------------------------
// Helpers (plain sm_100 PTX)
// ---------------------------------------------------------------------------
__device__ __forceinline__ uint32_t smem_u32(const void* p) {
    uint32_t a;
    asm("{ .reg .u64 t; cvta.to.shared.u64 t, %1; cvt.u32.u64 %0, t; }" : "=r"(a) : "l"(p));
    return a;
}
__device__ __forceinline__ void cpa16(uint32_t dst, const void* src) {
    asm volatile("cp.async.cg.shared.global [%0], [%1], 16;" :: "r"(dst), "l"(src));
}
#define CP_COMMIT() asm volatile("cp.async.commit_group;" ::: "memory")

#define LDSM4(r, addr) \
    asm volatile("ldmatrix.sync.aligned.m8n8.x4.shared.b16 {%0,%1,%2,%3}, [%4];" \
        : "=r"((r)[0]), "=r"((r)[1]), "=r"((r)[2]), "=r"((r)[3]) : "r"(addr))
#define LDSMT4(r, addr) \
    asm volatile("ldmatrix.sync.aligned.m8n8.x4.trans.shared.b16 {%0,%1,%2,%3}, [%4];" \
        : "=r"((r)[0]), "=r"((r)[1]), "=r"((r)[2]), "=r"((r)[3]) : "r"(addr))

#define MMA_F16(d, a, b0, b1) \
    asm volatile("mma.sync.aligned.m16n8k16.row.col.f32.f16.f16.f32 " \
        "{%0,%1,%2,%3}, {%4,%5,%6,%7}, {%8,%9}, {%0,%1,%2,%3};" \
        : "+f"((d)[0]), "+f"((d)[1]), "+f"((d)[2]), "+f"((d)[3]) \
        : "r"((a)[0]), "r"((a)[1]), "r"((a)[2]), "r"((a)[3]), "r"(b0), "r"(b1))

// two floats -> {fp16 hi pair, fp16 residual pair}
__device__ __forceinline__ void split2h(float a, float b, uint32_t& h, uint32_t& l) {
    __half2 hh = __floats2half2_rn(a, b);
    float2 hf = __half22float2(hh);
    __half2 ll = __floats2half2_rn(a - hf.x, b - hf.y);
    h = *(uint32_t*)&hh;
    l = *(uint32_t*)&ll;
}
__device__ __forceinline__ uint32_t pack2h(float a, float b) {
    __half2 hh = __floats2half2_rn(a, b);
    return *(uint32_t*)&hh;
}

// ---------------------------------------------------------------------------
// Conversions
// ---------------------------------------------------------------------------
__global__ void cvt_w(const float4* __restrict__ W0, const float4* __restrict__ W1,
                      const float4* __restrict__ W2, const float4* __restrict__ W3,
                      uint2* __restrict__ out)
{
    int i = blockIdx.x * blockDim.x + threadIdx.x;          // 0 .. 4*262144
    int z = i >> 18, j = i & 262143;
    const float4* W = (z == 0) ? W0 : (z == 1) ? W1 : (z == 2) ? W2 : W3;
    float4 v = W[j];
    union { h16 b[4]; uint2 u; } H;
    H.b[0] = __float2half(v.x); H.b[1] = __float2half(v.y);
    H.b[2] = __float2half(v.z); H.b[3] = __float2half(v.w);
    out[i] = H.u;
}

__global__ void cvt_split(const float4* __restrict__ in, uint2* __restrict__ hi,
                          uint2* __restrict__ lo, int n4)
{
    int i = blockIdx.x * blockDim.x + threadIdx.x;
    if (i >= n4) return;
    float4 v = in[i];
    float f[4] = {v.x, v.y, v.z, v.w};
    union { h16 b[4]; uint2 u; } H, L;
    #pragma unroll
    for (int j = 0; j < 4; j++) {
        h16 h = __float2half(f[j]);
        H.b[j] = h;
        L.b[j] = __float2half(f[j] - __half2float(h));
    }
    hi[i] = H.u;
    lo[i] = L.u;
}

// ---------------------------------------------------------------------------
// HMMA GEMM:  C = A @ W^T (+bias)   A = Ah + Al (fp16 exact split), W fp16.
// 2-MMA scheme: Ah*W + Al*W.  CTA 128x128, BK=32, 3 stages, single sync/iter.
// mode 0: fp32 out + bias.  mode 1: per-z epilogue, (acc+bias)*scale ->
//   hi/lo fp16 if L-pointer non-null, else single fp16.
// ---------------------------------------------------------------------------
#define STG_BYTES 30720                 // Ah | Al | Wh  (128 rows * 80B each)
#define GEMM_SMEM (3 * STG_BYTES + 128)

__global__ __launch_bounds__(256, 1) void gemm_mma(
    const h16* __restrict__ Ah, const h16* __restrict__ Al,
    const h16* __restrict__ Whb, int wbase,
    const float* __restrict__ bias0, const float* __restrict__ bias1, const float* __restrict__ bias2,
    float* __restrict__ C0, int mode,
    h16* H0, h16* L0, h16* H1, h16* L1, h16* H2, h16* L2,
    float s0, float s1, float s2)
{
    const int z = blockIdx.z;
    const float* bias = (z == 0) ? bias0 : (z == 1) ? bias1 : bias2;
    const h16* Wh = Whb + (size_t)(wbase + z) * D_MODEL * D_MODEL;

    const int m0 = blockIdx.y * 128;
    const int n0 = blockIdx.x * 128;
    const int tid  = threadIdx.x;
    const int w    = tid >> 5;
    const int lane = tid & 31;
    const int wm   = w & 1;
    const int wn   = w >> 1;

    extern __shared__ char dyn[];
    const uint32_t sb = (smem_u32(dyn) + 127u) & ~127u;

    auto load_stage = [&](int stage, int k0) {
        uint32_t base = sb + (uint32_t)stage * STG_BYTES;
        #pragma unroll
        for (int j = 0; j < 2; j++) {
            int id = tid * 2 + j;
            int r = id >> 2, c = id & 3;
            uint32_t off = (uint32_t)(r * 80 + c * 16);
            size_t ga = (size_t)(m0 + r) * D_MODEL + k0 + c * 8;
            size_t gw = (size_t)(n0 + r) * D_MODEL + k0 + c * 8;
            cpa16(base +         off, Ah + ga);
            cpa16(base + 10240 + off, Al + ga);
            cpa16(base + 20480 + off, Wh + gw);
        }
        CP_COMMIT();
    };

    load_stage(0, 0);
    load_stage(1, 32);

    float acc[4][4][4];
    #pragma unroll
    for (int i = 0; i < 4; i++)
        #pragma unroll
        for (int j = 0; j < 4; j++)
            #pragma unroll
            for (int q = 0; q < 4; q++) acc[i][j][q] = 0.f;

    const int arow = lane & 15;
    const int achk = (lane >> 4) * 16;

    const int NIT = D_MODEL / 32;       // 32
    for (int it = 0; it < NIT; it++) {
        if (it < NIT - 1) asm volatile("cp.async.wait_group 1;" ::: "memory");
        else              asm volatile("cp.async.wait_group 0;" ::: "memory");
        __syncthreads();
        // load into the buffer consumed in iter it-1 (safe after this barrier)
        if (it + 2 < NIT) load_stage((it + 2) % 3, (it + 2) * 32);

        uint32_t base = sb + (uint32_t)(it % 3) * STG_BYTES;
        uint32_t aoff = base +         (uint32_t)((wm * 64 + arow) * 80) + achk;
        uint32_t boff = base + 20480 + (uint32_t)((wn * 32 + arow) * 80) + achk;

        #pragma unroll
        for (int ks = 0; ks < 2; ks++) {
            uint32_t kadd = (uint32_t)(ks * 32);
            uint32_t a_h[4][4], a_l[4][4], b0[4], b1[4];
            #pragma unroll
            for (int mb = 0; mb < 4; mb++) {
                LDSM4(a_h[mb], aoff + kadd + (uint32_t)(mb * 16 * 80));
                LDSM4(a_l[mb], aoff + kadd + (uint32_t)(mb * 16 * 80) + 10240u);
            }
            LDSM4(b0, boff + kadd);
            LDSM4(b1, boff + kadd + (uint32_t)(16 * 80));

            #pragma unroll
            for (int mb = 0; mb < 4; mb++) {
                MMA_F16(acc[mb][0], a_h[mb], b0[0], b0[2]);
                MMA_F16(acc[mb][1], a_h[mb], b0[1], b0[3]);
                MMA_F16(acc[mb][2], a_h[mb], b1[0], b1[2]);
                MMA_F16(acc[mb][3], a_h[mb], b1[1], b1[3]);
            }
            #pragma unroll
            for (int mb = 0; mb < 4; mb++) {
                MMA_F16(acc[mb][0], a_l[mb], b0[0], b0[2]);
                MMA_F16(acc[mb][1], a_l[mb], b0[1], b0[3]);
                MMA_F16(acc[mb][2], a_l[mb], b1[0], b1[2]);
                MMA_F16(acc[mb][3], a_l[mb], b1[1], b1[3]);
            }
        }
    }

    if (mode == 0) {
        #pragma unroll
        for (int mb = 0; mb < 4; mb++) {
            int r0 = m0 + wm * 64 + mb * 16 + (lane >> 2);
            float* c0p = C0 + (size_t)r0 * D_MODEL;
            float* c1p = c0p + 8 * D_MODEL;
            #pragma unroll
            for (int nf = 0; nf < 4; nf++) {
                int col = n0 + wn * 32 + nf * 8 + (lane & 3) * 2;
                float b0 = bias[col], b1 = bias[col + 1];
                *(float2*)(c0p + col) = make_float2(acc[mb][nf][0] + b0, acc[mb][nf][1] + b1);
                *(float2*)(c1p + col) = make_float2(acc[mb][nf][2] + b0, acc[mb][nf][3] + b1);
            }
        }
    } else {
        h16* H = (z == 0) ? H0 : (z == 1) ? H1 : H2;
        h16* L = (z == 0) ? L0 : (z == 1) ? L1 : L2;
        float scl = (z == 0) ? s0 : (z == 1) ? s1 : s2;
        #pragma unroll
        for (int mb = 0; mb < 4; mb++) {
            int r0 = m0 + wm * 64 + mb * 16 + (lane >> 2);
            #pragma unroll
            for (int nf = 0; nf < 4; nf++) {
                int col = n0 + wn * 32 + nf * 8 + (lane & 3) * 2;
                float b0 = bias[col], b1 = bias[col + 1];
                float v00 = (acc[mb][nf][0] + b0) * scl, v01 = (acc[mb][nf][1] + b1) * scl;
                float v10 = (acc[mb][nf][2] + b0) * scl, v11 = (acc[mb][nf][3] + b1) * scl;
                if (L) {
                    uint32_t h0, l0, h1, l1;
                    split2h(v00, v01, h0, l0);
                    split2h(v10, v11, h1, l1);
                    *(uint32_t*)(H + (size_t)r0 * D_MODEL + col)       = h0;
                    *(uint32_t*)(L + (size_t)r0 * D_MODEL + col)       = l0;
                    *(uint32_t*)(H + (size_t)(r0 + 8) * D_MODEL + col) = h1;
                    *(uint32_t*)(L + (size_t)(r0 + 8) * D_MODEL + col) = l1;
                } else {
                    *(uint32_t*)(H + (size_t)r0 * D_MODEL + col)       = pack2h(v00, v01);
                    *(uint32_t*)(H + (size_t)(r0 + 8) * D_MODEL + col) = pack2h(v10, v11);
                }
            }
        }
    }
}

// ---------------------------------------------------------------------------
// Flash attention, fp16 HMMA.  Q = Qh+Ql (exact split), K, V single fp16.
// S = Qh*K + Ql*K (2 MMA); O += Ph*V + Pl*V (2 MMA, P split exact).
// CTA = 128 q-rows; KV tiles 64, 3 stages, single sync/iter.
// ---------------------------------------------------------------------------
#define SD        144
#define QH_S      0
#define QL_S      18432
#define STAGE0    36864
#define STAGE_SZ  18432               // K(9216) + V(9216)
#define AK        0
#define AV        9216
#define ATTN_SMEM (STAGE0 + 3 * STAGE_SZ + 128)   // ~92.3KB

__global__ __launch_bounds__(256, 1) void attn_mma(
    const h16* __restrict__ Qh, const h16* __restrict__ Ql,
    const h16* __restrict__ Kh, const h16* __restrict__ Vh,
    h16* __restrict__ Oh, h16* __restrict__ Ol)
{
    extern __shared__ char dyn[];
    const uint32_t sb = (smem_u32(dyn) + 127u) & ~127u;

    const int tid  = threadIdx.x;
    const int w    = tid >> 5;
    const int lane = tid & 31;
    const int b    = blockIdx.y >> 4;
    const int h    = blockIdx.y & 15;
    const int q0   = blockIdx.x * 128;

    // Q tile (hi+lo), own commit group
    #pragma unroll
    for (int t = 0; t < 8; t++) {
        int i = tid + t * 256;
        int arr = i >> 10, row = (i >> 3) & 127, ch = i & 7;
        size_t off = (size_t)(b * SEQ + q0 + row) * D_MODEL + h * 64 + ch * 8;
        const h16* src = arr ? Ql : Qh;
        cpa16(sb + (uint32_t)(arr ? QL_S : QH_S) + (uint32_t)(row * SD + ch * 16), src + off);
    }
    CP_COMMIT();

    auto load_kv = [&](int stage, int c0) {
        uint32_t base = sb + STAGE0 + (uint32_t)stage * STAGE_SZ;
        #pragma unroll
        for (int t = 0; t < 4; t++) {
            int i = tid + t * 256;
            int arr = i >> 9, r = (i >> 3) & 63, ch = i & 7;
            size_t off = (size_t)(b * SEQ + c0 + r) * D_MODEL + h * 64 + ch * 8;
            const h16* src = arr ? Vh : Kh;
            cpa16(base + (uint32_t)(arr * 9216 + r * SD + ch * 16), src + off);
        }
        CP_COMMIT();
    };
    load_kv(0, 0);
    load_kv(1, 64);

    // Q fragments (held in registers)
    asm volatile("cp.async.wait_group 2;" ::: "memory");
    __syncthreads();
    uint32_t qh[4][4], ql[4][4];
    {
        uint32_t qa = sb + (uint32_t)((w * 16 + (lane & 15)) * SD) + (uint32_t)((lane >> 4) * 16);
        #pragma unroll
        for (int kf = 0; kf < 4; kf++) {
            LDSM4(qh[kf], qa + QH_S + (uint32_t)(kf * 32));
            LDSM4(ql[kf], qa + QL_S + (uint32_t)(kf * 32));
        }
    }

    float oacc[8][4];
    #pragma unroll
    for (int i = 0; i < 8; i++)
        #pragma unroll
        for (int j = 0; j < 4; j++) oacc[i][j] = 0.f;
    float mrun[2] = {-1e30f, -1e30f};
    float lrun[2] = {0.f, 0.f};

    const uint32_t krow = (uint32_t)((lane & 15) * SD) + (uint32_t)((lane >> 4) * 16);
    const uint32_t vrow = (uint32_t)((((lane >> 3) & 1) * 8 + (lane & 7)) * SD)
                        + (uint32_t)(((lane >> 4) & 1) * 16);

    const int NT = SEQ / 64;   // 32
    for (int kt = 0; kt < NT; kt++) {
        if (kt < NT - 1) asm volatile("cp.async.wait_group 1;" ::: "memory");
        else             asm volatile("cp.async.wait_group 0;" ::: "memory");
        __syncthreads();
        if (kt + 2 < NT) load_kv((kt + 2) % 3, (kt + 2) * 64);

        uint32_t buf = sb + STAGE0 + (uint32_t)(kt % 3) * STAGE_SZ;

        // ---- S = Q K^T (2-term) ----
        float sacc[8][4];
        #pragma unroll
        for (int i = 0; i < 8; i++)
            #pragma unroll
            for (int j = 0; j < 4; j++) sacc[i][j] = 0.f;

        #pragma unroll
        for (int kf = 0; kf < 4; kf++) {
            uint32_t bh[4][4];
            #pragma unroll
            for (int g = 0; g < 4; g++) {
                uint32_t ka = buf + AK + (uint32_t)(g * 16 * SD) + krow + (uint32_t)(kf * 32);
                LDSM4(bh[g], ka);
            }
            #pragma unroll
            for (int g = 0; g < 4; g++) {
                MMA_F16(sacc[2 * g],     qh[kf], bh[g][0], bh[g][2]);
                MMA_F16(sacc[2 * g + 1], qh[kf], bh[g][1], bh[g][3]);
            }
            #pragma unroll
            for (int g = 0; g < 4; g++) {
                MMA_F16(sacc[2 * g],     ql[kf], bh[g][0], bh[g][2]);
                MMA_F16(sacc[2 * g + 1], ql[kf], bh[g][1], bh[g][3]);
            }
        }

        // ---- online softmax ----
        #pragma unroll
        for (int slot = 0; slot < 2; slot++) {
            const int o0 = slot * 2;
            float ml = -1e30f;
            #pragma unroll
            for (int nf = 0; nf < 8; nf++)
                ml = fmaxf(ml, fmaxf(sacc[nf][o0], sacc[nf][o0 + 1]));
            ml = fmaxf(ml, __shfl_xor_sync(0xffffffffu, ml, 1));
            ml = fmaxf(ml, __shfl_xor_sync(0xffffffffu, ml, 2));
            float mnew = fmaxf(mrun[slot], ml);
            float corr = __expf(mrun[slot] - mnew);
            float ls = 0.f;
            #pragma unroll
            for (int nf = 0; nf < 8; nf++) {
                sacc[nf][o0]     = __expf(sacc[nf][o0]     - mnew);
                sacc[nf][o0 + 1] = __expf(sacc[nf][o0 + 1] - mnew);
                ls += sacc[nf][o0] + sacc[nf][o0 + 1];
            }
            ls += __shfl_xor_sync(0xffffffffu, ls, 1);
            ls += __shfl_xor_sync(0xffffffffu, ls, 2);
            lrun[slot] = lrun[slot] * corr + ls;
            mrun[slot] = mnew;
            #pragma unroll
            for (int nf = 0; nf < 8; nf++) {
                oacc[nf][o0]     *= corr;
                oacc[nf][o0 + 1] *= corr;
            }
        }

        // ---- O += P V (2-term, P exact split) ----
        #pragma unroll
        for (int kf2 = 0; kf2 < 4; kf2++) {
            float* sA = sacc[2 * kf2];
            float* sB = sacc[2 * kf2 + 1];
            uint32_t ph[4], pl[4];
            split2h(sA[0], sA[1], ph[0], pl[0]);
            split2h(sA[2], sA[3], ph[1], pl[1]);
            split2h(sB[0], sB[1], ph[2], pl[2]);
            split2h(sB[2], sB[3], ph[3], pl[3]);

            uint32_t vr[4][4];
            #pragma unroll
            for (int g = 0; g < 4; g++) {
                uint32_t va = buf + AV + (uint32_t)(kf2 * 16 * SD) + vrow + (uint32_t)(g * 32);
                LDSMT4(vr[g], va);
            }
            #pragma unroll
            for (int g = 0; g < 4; g++) {
                MMA_F16(oacc[2 * g],     ph, vr[g][0], vr[g][1]);
                MMA_F16(oacc[2 * g + 1], ph, vr[g][2], vr[g][3]);
            }
            #pragma unroll
            for (int g = 0; g < 4; g++) {
                MMA_F16(oacc[2 * g],     pl, vr[g][0], vr[g][1]);
                MMA_F16(oacc[2 * g + 1], pl, vr[g][2], vr[g][3]);
            }
        }
    }

    // ---- epilogue: normalize + hi/lo split ----
    #pragma unroll
    for (int slot = 0; slot < 2; slot++) {
        float inv = 1.f / lrun[slot];
        size_t grow = (size_t)(b * SEQ + q0 + w * 16 + (lane >> 2) + slot * 8);
        #pragma unroll
        for (int nf = 0; nf < 8; nf++) {
            int col = h * 64 + nf * 8 + (lane & 3) * 2;
            uint32_t hw, lw;
            split2h(oacc[nf][slot * 2] * inv, oacc[nf][slot * 2 + 1] * inv, hw, lw);
            *(uint32_t*)(Oh + grow * D_MODEL + col) = hw;
            *(uint32_t*)(Ol + grow * D_MODEL + col) = lw;
        }
    }
}

// ---------------------------------------------------------------------------
extern "C" void kernel_launch(void* const* d_in, const int* in_sizes, int n_in,
                              void* d_out, int out_size)
{
    const float* x  = (const float*)d_in[0];
    const float* Wq = (const float*)d_in[1];
    const float* bq = (const float*)d_in[2];
    const float* Wk = (const float*)d_in[3];
    const float* bk = (const float*)d_in[4];
    const float* Wv = (const float*)d_in[5];
    const float* bv = (const float*)d_in[6];
    const float* Wo = (const float*)d_in[7];
    const float* bo = (const float*)d_in[8];

    h16 *Ah, *Al, *Wh, *Qh, *Ql, *Kh, *Vh;
    cudaGetSymbolAddress((void**)&Ah, g_Ah);
    cudaGetSymbolAddress((void**)&Al, g_Al);
    cudaGetSymbolAddress((void**)&Wh, g_Wh);
    cudaGetSymbolAddress((void**)&Qh, g_Qh);
    cudaGetSymbolAddress((void**)&Ql, g_Ql);
    cudaGetSymbolAddress((void**)&Kh, g_Kh);
    cudaGetSymbolAddress((void**)&Vh, g_Vh);

    cudaFuncSetAttribute(gemm_mma, cudaFuncAttributeMaxDynamicSharedMemorySize, GEMM_SMEM);
    cudaFuncSetAttribute(attn_mma, cudaFuncAttributeMaxDynamicSharedMemorySize, ATTN_SMEM);

    // conversions: weights (single fp16, fused) + x (hi/lo split)
    cvt_w<<<4 * 262144 / 256, 256>>>((const float4*)Wq, (const float4*)Wk,
                                     (const float4*)Wv, (const float4*)Wo, (uint2*)Wh);
    const int NX4 = M_TOT * D_MODEL / 4;
    cvt_split<<<NX4 / 256, 256>>>((const float4*)x, (uint2*)Ah, (uint2*)Al, NX4);

    // Q/K/V projections: Q -> hi/lo scaled 1/8, K/V -> single fp16
    dim3 gqkv(D_MODEL / 128, M_TOT / 128, 3);
    gemm_mma<<<gqkv, 256, GEMM_SMEM>>>(Ah, Al, Wh, 0, bq, bk, bv,
                                       nullptr, 1,
                                       Qh, Ql, Kh, nullptr, Vh, nullptr,
                                       0.125f, 1.f, 1.f);

    // attention -> hi/lo fp16 into Ah/Al
    dim3 gattn(SEQ / 128, BATCH * NUM_HEADS);
    attn_mma<<<gattn, 256, ATTN_SMEM>>>(Qh, Ql, Kh, Vh, Ah, Al);

    // output projection -> fp32 d_out
    dim3 gout(D_MODEL / 128, M_TOT / 128, 1);
    gemm_mma<<<gout, 256, GEMM_SMEM>>>(Ah, Al, Wh, 3, bo, bo, bo,
                                       (float*)d_out, 0,
                                       nullptr, nullptr, nullptr, nullptr, nullptr, nullptr,
                                       1.f, 1.f, 1.f);
}

// round 6
// speedup vs baseline: 4.8221x; 1.1077x over previous
#include <cuda_runtime.h>
#include <cuda_fp16.h>
#include <stdint.h>
#include <math.h>

#define D_MODEL   1024
#define NUM_HEADS 16
#define BATCH     4
#define SEQ       2048
#define M_TOT     (BATCH * SEQ)   // 8192

typedef __half h16;

// ---------------------------------------------------------------------------
// Scratch (allocation-free: device globals)
// ---------------------------------------------------------------------------
__device__ h16 g_Ah[M_TOT * D_MODEL];        // A-operand hi (x, then attn out)
__device__ h16 g_Al[M_TOT * D_MODEL];        // A-operand lo
__device__ h16 g_Wh[4 * D_MODEL * D_MODEL];  // weights, single fp16
__device__ h16 g_Qh[M_TOT * D_MODEL];
__device__ h16 g_Ql[M_TOT * D_MODEL];
__device__ h16 g_Kh[M_TOT * D_MODEL];
__device__ h16 g_Vh[M_TOT * D_MODEL];

// ---------------------------------------------------------------------------
// Helpers
// ---------------------------------------------------------------------------
__device__ __forceinline__ uint32_t smem_u32(const void* p) {
    uint32_t a;
    asm("{ .reg .u64 t; cvta.to.shared.u64 t, %1; cvt.u32.u64 %0, t; }" : "=r"(a) : "l"(p));
    return a;
}
__device__ __forceinline__ void cpa16(uint32_t dst, const void* src) {
    asm volatile("cp.async.cg.shared.global [%0], [%1], 16;" :: "r"(dst), "l"(src));
}
#define CP_COMMIT() asm volatile("cp.async.commit_group;" ::: "memory")

#define LDSM4(r, addr) \
    asm volatile("ldmatrix.sync.aligned.m8n8.x4.shared.b16 {%0,%1,%2,%3}, [%4];" \
        : "=r"((r)[0]), "=r"((r)[1]), "=r"((r)[2]), "=r"((r)[3]) : "r"(addr))
#define LDSMT4(r, addr) \
    asm volatile("ldmatrix.sync.aligned.m8n8.x4.trans.shared.b16 {%0,%1,%2,%3}, [%4];" \
        : "=r"((r)[0]), "=r"((r)1[0]*0, "=r"((r)[2]), "=r"((r)[3]) : "r"(addr))
#undef LDSMT4
#define LDSMT4(r, addr) \
    asm volatile("ldmatrix.sync.aligned.m8n8.x4.trans.shared.b16 {%0,%1,%2,%3}, [%4];" \
        : "=r"((r)[0]), "=r"((r)[1]), "=r"((r)[2]), "=r"((r)[3]) : "r"(addr))

#define MMA_F16(d, a, b0, b1) \
    asm volatile("mma.sync.aligned.m16n8k16.row.col.f32.f16.f16.f32 " \
        "{%0,%1,%2,%3}, {%4,%5,%6,%7}, {%8,%9}, {%0,%1,%2,%3};" \
        : "+f"((d)[0]), "+f"((d)[1]), "+f"((d)[2]), "+f"((d)[3]) \
        : "r"((a)[0]), "r"((a)[1]), "r"((a)[2]), "r"((a)[3]), "r"(b0), "r"(b1))

__device__ __forceinline__ void split2h(float a, float b, uint32_t& h, uint32_t& l) {
    __half2 hh = __floats2half2_rn(a, b);
    float2 hf = __half22float2(hh);
    __half2 ll = __floats2half2_rn(a - hf.x, b - hf.y);
    h = *(uint32_t*)&hh;
    l = *(uint32_t*)&ll;
}
__device__ __forceinline__ uint32_t pack2h(float a, float b) {
    __half2 hh = __floats2half2_rn(a, b);
    return *(uint32_t*)&hh;
}

// ---------------------------------------------------------------------------
// Conversions
// ---------------------------------------------------------------------------
__global__ void cvt_w(const float4* __restrict__ W0, const float4* __restrict__ W1,
                      const float4* __restrict__ W2, const float4* __restrict__ W3,
                      uint2* __restrict__ out)
{
    int i = blockIdx.x * blockDim.x + threadIdx.x;
    int z = i >> 18, j = i & 262143;
    const float4* W = (z == 0) ? W0 : (z == 1) ? W1 : (z == 2) ? W2 : W3;
    float4 v = W[j];
    union { h16 b[4]; uint2 u; } H;
    H.b[0] = __float2half(v.x); H.b[1] = __float2half(v.y);
    H.b[2] = __float2half(v.z); H.b[3] = __float2half(v.w);
    out[i] = H.u;
}

__global__ void cvt_split(const float4* __restrict__ in, uint2* __restrict__ hi,
                          uint2* __restrict__ lo, int n4)
{
    int i = blockIdx.x * blockDim.x + threadIdx.x;
    if (i >= n4) return;
    float4 v = in[i];
    float f[4] = {v.x, v.y, v.z, v.w};
    union { h16 b[4]; uint2 u; } H, L;
    #pragma unroll
    for (int j = 0; j < 4; j++) {
        h16 h = __float2half(f[j]);
        H.b[j] = h;
        L.b[j] = __float2half(f[j] - __half2float(h));
    }
    hi[i] = H.u;
    lo[i] = L.u;
}

// ---------------------------------------------------------------------------
// HMMA GEMM:  C = A @ W^T (+bias)   A = Ah + Al (fp16 split), W fp16. 2-MMA.
// CTA 128x128, BK=32, 3 stages, single sync/iter, 2 CTAs/SM.
// ---------------------------------------------------------------------------
#define STG_BYTES 30720
#define GEMM_SMEM (3 * STG_BYTES + 128)

__global__ __launch_bounds__(256, 2) void gemm_mma(
    const h16* __restrict__ Ah, const h16* __restrict__ Al,
    const h16* __restrict__ Whb, int wbase,
    const float* __restrict__ bias0, const float* __restrict__ bias1, const float* __restrict__ bias2,
    float* __restrict__ C0, int mode,
    h16* H0, h16* L0, h16* H1, h16* L1, h16* H2, h16* L2,
    float s0, float s1, float s2)
{
    const int z = blockIdx.z;
    const float* bias = (z == 0) ? bias0 : (z == 1) ? bias1 : bias2;
    const h16* Wh = Whb + (size_t)(wbase + z) * D_MODEL * D_MODEL;

    const int m0 = blockIdx.y * 128;
    const int n0 = blockIdx.x * 128;
    const int tid  = threadIdx.x;
    const int w    = tid >> 5;
    const int lane = tid & 31;
    const int wm   = w & 1;
    const int wn   = w >> 1;

    extern __shared__ char dyn[];
    const uint32_t sb = (smem_u32(dyn) + 127u) & ~127u;

    auto load_stage = [&](int stage, int k0) {
        uint32_t base = sb + (uint32_t)stage * STG_BYTES;
        #pragma unroll
        for (int j = 0; j < 2; j++) {
            int id = tid * 2 + j;
            int r = id >> 2, c = id & 3;
            uint32_t off = (uint32_t)(r * 80 + c * 16);
            size_t ga = (size_t)(m0 + r) * D_MODEL + k0 + c * 8;
            size_t gw = (size_t)(n0 + r) * D_MODEL + k0 + c * 8;
            cpa16(base +         off, Ah + ga);
            cpa16(base + 10240 + off, Al + ga);
            cpa16(base + 20480 + off, Wh + gw);
        }
        CP_COMMIT();
    };

    load_stage(0, 0);
    load_stage(1, 32);

    float acc[4][4][4];
    #pragma unroll
    for (int i = 0; i < 4; i++)
        #pragma unroll
        for (int j = 0; j < 4; j++)
            #pragma unroll
            for (int q = 0; q < 4; q++) acc[i][j][q] = 0.f;

    const int arow = lane & 15;
    const int achk = (lane >> 4) * 16;

    const int NIT = D_MODEL / 32;
    for (int it = 0; it < NIT; it++) {
        if (it < NIT - 1) asm volatile("cp.async.wait_group 1;" ::: "memory");
        else              asm volatile("cp.async.wait_group 0;" ::: "memory");
        __syncthreads();
        if (it + 2 < NIT) load_stage((it + 2) % 3, (it + 2) * 32);

        uint32_t base = sb + (uint32_t)(it % 3) * STG_BYTES;
        uint32_t aoff = base +         (uint32_t)((wm * 64 + arow) * 80) + achk;
        uint32_t boff = base + 20480 + (uint32_t)((wn * 32 + arow) * 80) + achk;

        #pragma unroll
        for (int ks = 0; ks < 2; ks++) {
            uint32_t kadd = (uint32_t)(ks * 32);
            uint32_t a_h[4][4], a_l[4][4], b0[4], b1[4];
            #pragma unroll
            for (int mb = 0; mb < 4; mb++) {
                LDSM4(a_h[mb], aoff + kadd + (uint32_t)(mb * 16 * 80));
                LDSM4(a_l[mb], aoff + kadd + (uint32_t)(mb * 16 * 80) + 10240u);
            }
            LDSM4(b0, boff + kadd);
            LDSM4(b1, boff + kadd + (uint32_t)(16 * 80));

            #pragma unroll
            for (int mb = 0; mb < 4; mb++) {
                MMA_F16(acc[mb][0], a_h[mb], b0[0], b0[2]);
                MMA_F16(acc[mb][1], a_h[mb], b0[1], b0[3]);
                MMA_F16(acc[mb][2], a_h[mb], b1[0], b1[2]);
                MMA_F16(acc[mb][3], a_h[mb], b1[1], b1[3]);
            }
            #pragma unroll
            for (int mb = 0; mb < 4; mb++) {
                MMA_F16(acc[mb][0], a_l[mb], b0[0], b0[2]);
                MMA_F16(acc[mb][1], a_l[mb], b0[1], b0[3]);
                MMA_F16(acc[mb][2], a_l[mb], b1[0], b1[2]);
                MMA_F16(acc[mb][3], a_l[mb], b1[1], b1[3]);
            }
        }
    }

    if (mode == 0) {
        #pragma unroll
        for (int mb = 0; mb < 4; mb++) {
            int r0 = m0 + wm * 64 + mb * 16 + (lane >> 2);
            float* c0p = C0 + (size_t)r0 * D_MODEL;
            float* c1p = c0p + 8 * D_MODEL;
            #pragma unroll
            for (int nf = 0; nf < 4; nf++) {
                int col = n0 + wn * 32 + nf * 8 + (lane & 3) * 2;
                float b0 = bias[col], b1 = bias[col + 1];
                *(float2*)(c0p + col) = make_float2(acc[mb][nf][0] + b0, acc[mb][nf][1] + b1);
                *(float2*)(c1p + col) = make_float2(acc[mb][nf][2] + b0, acc[mb][nf][3] + b1);
            }
        }
    } else {
        h16* H = (z == 0) ? H0 : (z == 1) ? H1 : H2;
        h16* L = (z == 0) ? L0 : (z == 1) ? L1 : L2;
        float scl = (z == 0) ? s0 : (z == 1) ? s1 : s2;
        #pragma unroll
        for (int mb = 0; mb < 4; mb++) {
            int r0 = m0 + wm * 64 + mb * 16 + (lane >> 2);
            #pragma unroll
            for (int nf = 0; nf < 4; nf++) {
                int col = n0 + wn * 32 + nf * 8 + (lane & 3) * 2;
                float b0 = bias[col], b1 = bias[col + 1];
                float v00 = (acc[mb][nf][0] + b0) * scl, v01 = (acc[mb][nf][1] + b1) * scl;
                float v10 = (acc[mb][nf][2] + b0) * scl, v11 = (acc[mb][nf][3] + b1) * scl;
                if (L) {
                    uint32_t h0, l0, h1, l1;
                    split2h(v00, v01, h0, l0);
                    split2h(v10, v11, h1, l1);
                    *(uint32_t*)(H + (size_t)r0 * D_MODEL + col)       = h0;
                    *(uint32_t*)(L + (size_t)r0 * D_MODEL + col)       = l0;
                    *(uint32_t*)(H + (size_t)(r0 + 8) * D_MODEL + col) = h1;
                    *(uint32_t*)(L + (size_t)(r0 + 8) * D_MODEL + col) = l1;
                } else {
                    *(uint32_t*)(H + (size_t)r0 * D_MODEL + col)       = pack2h(v00, v01);
                    *(uint32_t*)(H + (size_t)(r0 + 8) * D_MODEL + col) = pack2h(v10, v11);
                }
            }
        }
    }
}

// ---------------------------------------------------------------------------
// Flash attention, fp16 HMMA.  Q = Qh+Ql (pre-scaled by 0.125*log2e),
// K, V single fp16.  S = Qh*K + Ql*K; softmax in log2 domain (exp2f);
// O += P*V single-term (P fp16).  Q frags re-read from smem each tile
// (cuts regs -> 2 CTAs/SM).  2 CTAs/SM, 3-stage KV pipeline.
// ---------------------------------------------------------------------------
#define SD        144
#define QH_S      0
#define QL_S      18432
#define STAGE0    36864
#define STAGE_SZ  18432
#define AK        0
#define AV        9216
#define ATTN_SMEM (STAGE0 + 3 * STAGE_SZ + 128)

__global__ __launch_bounds__(256, 2) void attn_mma(
    const h16* __restrict__ Qh, const h16* __restrict__ Ql,
    const h16* __restrict__ Kh, const h16* __restrict__ Vh,
    h16* __restrict__ Oh, h16* __restrict__ Ol)
{
    extern __shared__ char dyn[];
    const uint32_t sb = (smem_u32(dyn) + 127u) & ~127u;

    const int tid  = threadIdx.x;
    const int w    = tid >> 5;
    const int lane = tid & 31;
    const int b    = blockIdx.y >> 4;
    const int h    = blockIdx.y & 15;
    const int q0   = blockIdx.x * 128;

    #pragma unroll
    for (int t = 0; t < 8; t++) {
        int i = tid + t * 256;
        int arr = i >> 10, row = (i >> 3) & 127, ch = i & 7;
        size_t off = (size_t)(b * SEQ + q0 + row) * D_MODEL + h * 64 + ch * 8;
        const h16* src = arr ? Ql : Qh;
        cpa16(sb + (uint32_t)(arr ? QL_S : QH_S) + (uint32_t)(row * SD + ch * 16), src + off);
    }
    CP_COMMIT();

    auto load_kv = [&](int stage, int c0) {
        uint32_t base = sb + STAGE0 + (uint32_t)stage * STAGE_SZ;
        #pragma unroll
        for (int t = 0; t < 4; t++) {
            int i = tid + t * 256;
            int arr = i >> 9, r = (i >> 3) & 63, ch = i & 7;
            size_t off = (size_t)(b * SEQ + c0 + r) * D_MODEL + h * 64 + ch * 8;
            const h16* src = arr ? Vh : Kh;
            cpa16(base + (uint32_t)(arr * 9216 + r * SD + ch * 16), src + off);
        }
        CP_COMMIT();
    };
    load_kv(0, 0);
    load_kv(1, 64);

    float oacc[8][4];
    #pragma unroll
    for (int i = 0; i < 8; i++)
        #pragma unroll
        for (int j = 0; j < 4; j++) oacc[i][j] = 0.f;
    float mrun[2] = {-1e30f, -1e30f};
    float lrun[2] = {0.f, 0.f};

    const uint32_t qa   = sb + (uint32_t)((w * 16 + (lane & 15)) * SD) + (uint32_t)((lane >> 4) * 16);
    const uint32_t krow = (uint32_t)((lane & 15) * SD) + (uint32_t)((lane >> 4) * 16);
    const uint32_t vrow = (uint32_t)((((lane >> 3) & 1) * 8 + (lane & 7)) * SD)
                        + (uint32_t)(((lane >> 4) & 1) * 16);

    const int NT = SEQ / 64;
    for (int kt = 0; kt < NT; kt++) {
        if (kt == 0)          asm volatile("cp.async.wait_group 2;" ::: "memory");
        else if (kt < NT - 1) asm volatile("cp.async.wait_group 1;" ::: "memory");
        else                  asm volatile("cp.async.wait_group 0;" ::: "memory");
        __syncthreads();
        if (kt + 2 < NT) load_kv((kt + 2) % 3, (kt + 2) * 64);

        uint32_t buf = sb + STAGE0 + (uint32_t)(kt % 3) * STAGE_SZ;

        // ---- S = Q K^T (Q 2-term, K single) ----
        float sacc[8][4];
        #pragma unroll
        for (int i = 0; i < 8; i++)
            #pragma unroll
            for (int j = 0; j < 4; j++) sacc[i][j] = 0.f;

        #pragma unroll
        for (int kf = 0; kf < 4; kf++) {
            uint32_t qhf[4], qlf[4], bh[4][4];
            LDSM4(qhf, qa + QH_S + (uint32_t)(kf * 32));
            LDSM4(qlf, qa + QL_S + (uint32_t)(kf * 32));
            #pragma unroll
            for (int g = 0; g < 4; g++) {
                uint32_t ka = buf + AK + (uint32_t)(g * 16 * SD) + krow + (uint32_t)(kf * 32);
                LDSM4(bh[g], ka);
            }
            #pragma unroll
            for (int g = 0; g < 4; g++) {
                MMA_F16(sacc[2 * g],     qhf, bh[g][0], bh[g][2]);
                MMA_F16(sacc[2 * g + 1], qhf, bh[g][1], bh[g][3]);
            }
            #pragma unroll
            for (int g = 0; g < 4; g++) {
                MMA_F16(sacc[2 * g],     qlf, bh[g][0], bh[g][2]);
                MMA_F16(sacc[2 * g + 1], qlf, bh[g][1], bh[g][3]);
            }
        }

        // ---- online softmax (log2 domain) ----
        #pragma unroll
        for (int slot = 0; slot < 2; slot++) {
            const int o0 = slot * 2;
            float ml = -1e30f;
            #pragma unroll
            for (int nf = 0; nf < 8; nf++)
                ml = fmaxf(ml, fmaxf(sacc[nf][o0], sacc[nf][o0 + 1]));
            ml = fmaxf(ml, __shfl_xor_sync(0xffffffffu, ml, 1));
            ml = fmaxf(ml, __shfl_xor_sync(0xffffffffu, ml, 2));
            float mnew = fmaxf(mrun[slot], ml);
            float corr = exp2f(mrun[slot] - mnew);
            float ls = 0.f;
            #pragma unroll
            for (int nf = 0; nf < 8; nf++) {
                sacc[nf][o0]     = exp2f(sacc[nf][o0]     - mnew);
                sacc[nf][o0 + 1] = exp2f(sacc[nf][o0 + 1] - mnew);
                ls += sacc[nf][o0] + sacc[nf][o0 + 1];
            }
            ls += __shfl_xor_sync(0xffffffffu, ls, 1);
            ls += __shfl_xor_sync(0xffffffffu, ls, 2);
            lrun[slot] = lrun[slot] * corr + ls;
            mrun[slot] = mnew;
            #pragma unroll
            for (int nf = 0; nf < 8; nf++) {
                oacc[nf][o0]     *= corr;
                oacc[nf][o0 + 1] *= corr;
            }
        }

        // ---- O += P V (single term) ----
        #pragma unroll
        for (int kf2 = 0; kf2 < 4; kf2++) {
            float* sA = sacc[2 * kf2];
            float* sB = sacc[2 * kf2 + 1];
            uint32_t ph[4];
            ph[0] = pack2h(sA[0], sA[1]);
            ph[1] = pack2h(sA[2], sA[3]);
            ph[2] = pack2h(sB[0], sB[1]);
            ph[3] = pack2h(sB[2], sB[3]);

            uint32_t vr[4][4];
            #pragma unroll
            for (int g = 0; g < 4; g++) {
                uint32_t va = buf + AV + (uint32_t)(kf2 * 16 * SD) + vrow + (uint32_t)(g * 32);
                LDSMT4(vr[g], va);
            }
            #pragma unroll
            for (int g = 0; g < 4; g++) {
                MMA_F16(oacc[2 * g],     ph, vr[g][0], vr[g][1]);
                MMA_F16(oacc[2 * g + 1], ph, vr[g][2], vr[g][3]);
            }
        }
    }

    // ---- epilogue ----
    #pragma unroll
    for (int slot = 0; slot < 2; slot++) {
        float inv = 1.f / lrun[slot];
        size_t grow = (size_t)(b * SEQ + q0 + w * 16 + (lane >> 2) + slot * 8);
        #pragma unroll
        for (int nf = 0; nf < 8; nf++) {
            int col = h * 64 + nf * 8 + (lane & 3) * 2;
            uint32_t hw, lw;
            split2h(oacc[nf][slot * 2] * inv, oacc[nf][slot * 2 + 1] * inv, hw, lw);
            *(uint32_t*)(Oh + grow * D_MODEL + col) = hw;
            *(uint32_t*)(Ol + grow * D_MODEL + col) = lw;
        }
    }
}

// ---------------------------------------------------------------------------
extern "C" void kernel_launch(void* const* d_in, const int* in_sizes, int n_in,
                              void* d_out, int out_size)
{
    const float* x  = (const float*)d_in[0];
    const float* Wq = (const float*)d_in[1];
    const float* bq = (const float*)d_in[2];
    const float* Wk = (const float*)d_in[3];
    const float* bk = (const float*)d_in[4];
    const float* Wv = (const float*)d_in[5];
    const float* bv = (const float*)d_in[6];
    const float* Wo = (const float*)d_in[7];
    const float* bo = (const float*)d_in[8];

    h16 *Ah, *Al, *Wh, *Qh, *Ql, *Kh, *Vh;
    cudaGetSymbolAddress((void**)&Ah, g_Ah);
    cudaGetSymbolAddress((void**)&Al, g_Al);
    cudaGetSymbolAddress((void**)&Wh, g_Wh);
    cudaGetSymbolAddress((void**)&Qh, g_Qh);
    cudaGetSymbolAddress((void**)&Ql, g_Ql);
    cudaGetSymbolAddress((void**)&Kh, g_Kh);
    cudaGetSymbolAddress((void**)&Vh, g_Vh);

    cudaFuncSetAttribute(gemm_mma, cudaFuncAttributeMaxDynamicSharedMemorySize, GEMM_SMEM);
    cudaFuncSetAttribute(attn_mma, cudaFuncAttributeMaxDynamicSharedMemorySize, ATTN_SMEM);

    cvt_w<<<4 * 262144 / 256, 256>>>((const float4*)Wq, (const float4*)Wk,
                                     (const float4*)Wv, (const float4*)Wo, (uint2*)Wh);
    const int NX4 = M_TOT * D_MODEL / 4;
    cvt_split<<<NX4 / 256, 256>>>((const float4*)x, (uint2*)Ah, (uint2*)Al, NX4);

    // Q/K/V: Q -> hi/lo scaled by 0.125*log2(e) (log2-domain softmax), K/V -> fp16
    dim3 gqkv(D_MODEL / 128, M_TOT / 128, 3);
    gemm_mma<<<gqkv, 256, GEMM_SMEM>>>(Ah, Al, Wh, 0, bq, bk, bv,
                                       nullptr, 1,
                                       Qh, Ql, Kh, nullptr, Vh, nullptr,
                                       0.18033688f, 1.f, 1.f);

    dim3 gattn(SEQ / 128, BATCH * NUM_HEADS);
    attn_mma<<<gattn, 256, ATTN_SMEM>>>(Qh, Ql, Kh, Vh, Ah, Al);

    dim3 gout(D_MODEL / 128, M_TOT / 128, 1);
    gemm_mma<<<gout, 256, GEMM_SMEM>>>(Ah, Al, Wh, 3, bo, bo, bo,
                                       (float*)d_out, 0,
                                       nullptr, nullptr, nullptr, nullptr, nullptr, nullptr,
                                       1.f, 1.f, 1.f);
}